// round 2
// baseline (speedup 1.0000x reference)
#include <cuda_runtime.h>
#include <cuda_bf16.h>
#include <math.h>

typedef unsigned long long ull;

// ---------------------------------------------------------------------------
// Problem dims
// ---------------------------------------------------------------------------
#define BB 8
#define LL 2048
#define HH 512
#define NN 64
#define PP (BB * LL)          // 16384 tokens

// ---------------------------------------------------------------------------
// Scratch (device globals — no allocation allowed)
// ---------------------------------------------------------------------------
__device__ float g_xT[BB * HH * LL];     // x transposed (B,H,L)
__device__ float g_yact[BB * HH * LL];   // gelu(scan + D*u), (B,H,L)
__device__ float g_z[PP * 2 * HH];       // GEMM1 out (P, 1024)
__device__ float g_xn[PP * HH];          // after GLU+res+LN1
__device__ float g_h1[PP * HH];          // FFN hidden
__device__ float g_y3[PP * HH];          // FFN out

// ---------------------------------------------------------------------------
// Packed f32x2 helpers
// ---------------------------------------------------------------------------
__device__ __forceinline__ ull pk(float x, float y) {
    ull r; asm("mov.b64 %0, {%1,%2};" : "=l"(r) : "f"(x), "f"(y)); return r;
}
__device__ __forceinline__ void upk(ull v, float& x, float& y) {
    asm("mov.b64 {%0,%1}, %2;" : "=f"(x), "=f"(y) : "l"(v));
}
__device__ __forceinline__ ull fma2(ull a, ull b, ull c) {
    ull d; asm("fma.rn.f32x2 %0, %1, %2, %3;" : "=l"(d) : "l"(a), "l"(b), "l"(c)); return d;
}
__device__ __forceinline__ ull mul2(ull a, ull b) {
    ull d; asm("mul.rn.f32x2 %0, %1, %2;" : "=l"(d) : "l"(a), "l"(b)); return d;
}

// ---------------------------------------------------------------------------
// K1: transpose (B,L,H) -> (B,H,L)
// ---------------------------------------------------------------------------
__global__ __launch_bounds__(256) void transpose_kernel(const float* __restrict__ x) {
    __shared__ float t[32][33];
    int b = blockIdx.z;
    int l0 = blockIdx.x * 32;
    int h0 = blockIdx.y * 32;
    int tx = threadIdx.x, ty = threadIdx.y;  // 32 x 8
#pragma unroll
    for (int j = 0; j < 4; j++) {
        int l = l0 + ty + j * 8;
        t[ty + j * 8][tx] = x[((long)(b * LL + l)) * HH + h0 + tx];
    }
    __syncthreads();
#pragma unroll
    for (int j = 0; j < 4; j++) {
        int h = h0 + ty + j * 8;
        g_xT[((long)(b * HH + h)) * LL + l0 + tx] = t[tx][ty + j * 8];
    }
}

// ---------------------------------------------------------------------------
// K2: SSM scan + D-skip + gelu(tanh).  One warp per (b,h).
// ---------------------------------------------------------------------------
__global__ __launch_bounds__(128) void scan_kernel(
    const float* __restrict__ log_dt, const float* __restrict__ A_re,
    const float* __restrict__ A_im, const float* __restrict__ C_re,
    const float* __restrict__ C_im, const float* __restrict__ D_skip) {
    int warp = threadIdx.x >> 5, lane = threadIdx.x & 31;
    int wg = blockIdx.x * 4 + warp;
    int b = wg >> 9, h = wg & 511;

    __shared__ float us[4][32];
    __shared__ float P[4][32 * 33];
    float* Pw = P[warp];
    float* uw = us[warp];

    float dt = expf(log_dt[h]);
    float wr_[2], wi_[2], c2r_[2], c2i_[2];
#pragma unroll
    for (int s = 0; s < 2; s++) {
        int n = lane + 32 * s;
        float ar = A_re[h * NN + n], ai = A_im[h * NN + n];
        float dr = dt * ar, di = dt * ai;
        float e = expf(dr);
        float sn, cs; sincosf(di, &sn, &cs);
        float wre = e * cs, wim = e * sn;
        float inv = 1.0f / (ar * ar + ai * ai);
        float qr = ((wre - 1.0f) * ar + wim * ai) * inv;
        float qi = (wim * ar - (wre - 1.0f) * ai) * inv;
        float cr = C_re[h * NN + n], ci = C_im[h * NN + n];
        c2r_[s] = 2.0f * (cr * qr - ci * qi);
        c2i_[s] = 2.0f * (cr * qi + ci * qr);
        wr_[s] = wre; wi_[s] = wim;
    }
    ull Wre  = pk(wr_[0], wr_[1]);
    ull Wim  = pk(wi_[0], wi_[1]);
    ull nWim = pk(-wi_[0], -wi_[1]);
    ull C2r  = pk(c2r_[0], c2r_[1]);
    ull nC2i = pk(-c2i_[0], -c2i_[1]);
    ull sre = pk(0.f, 0.f), sim = pk(0.f, 0.f);
    float Dh = D_skip[h];

    const float* ub = g_xT + ((long)(b * HH + h)) * LL;
    float* yb = g_yact + ((long)(b * HH + h)) * LL;

    for (int l0 = 0; l0 < LL; l0 += 32) {
        float umine = ub[l0 + lane];
        uw[lane] = umine;
        __syncwarp();
#pragma unroll
        for (int t = 0; t < 32; t++) {
            float u = uw[t];
            ull up = pk(u, u);
            ull tre = fma2(nWim, sim, up);
            ull srn = fma2(Wre, sre, tre);
            ull tim = mul2(Wim, sre);
            sim = fma2(Wre, sim, tim);
            sre = srn;
            ull pp = mul2(C2r, sre);
            pp = fma2(nC2i, sim, pp);
            float px, py; upk(pp, px, py);
            Pw[t * 33 + lane] = px + py;
        }
        __syncwarp();
        float s0 = 0, s1 = 0, s2 = 0, s3 = 0;
#pragma unroll
        for (int i = 0; i < 32; i += 4) {
            s0 += Pw[lane * 33 + i];
            s1 += Pw[lane * 33 + i + 1];
            s2 += Pw[lane * 33 + i + 2];
            s3 += Pw[lane * 33 + i + 3];
        }
        float yv = (s0 + s1) + (s2 + s3) + Dh * umine;
        // JAX default gelu: tanh approximation
        float t3 = yv * yv * yv;
        float g = 0.5f * yv * (1.0f + tanhf(0.7978845608028654f * (yv + 0.044715f * t3)));
        yb[l0 + lane] = g;
        __syncwarp();
    }
}

// ---------------------------------------------------------------------------
// SGEMM: C[m,n] = sum_k A[.,.] * B[n,k] (+bias[n], optional relu)
// A_KMAJOR:  A[k*lda + m]   (GEMM1: y_act is (H,L) per batch)
// !A_KMAJOR: A[m*lda + k]   (row-major activations)
// B is always row-major [n][K].
// Tiles: BM=BN=128, BK=16, 256 threads, 8x8 per thread, packed f32x2 FMAs.
// ---------------------------------------------------------------------------
template <bool A_KMAJOR, bool RELU>
__global__ __launch_bounds__(256) void sgemm_kernel(
    const float* __restrict__ A, const float* __restrict__ Bm,
    const float* __restrict__ bias, float* __restrict__ C,
    int K, int lda, int ldc, long strideA, long strideC) {
    constexpr int BM = 128, BK = 16;
    constexpr int AS = BM + 2;  // 130: keeps 8B alignment, conflict-free T-stores
    __shared__ float As[BK * AS];
    __shared__ float Bs[BK * AS];

    const float* Ab = A + (long)blockIdx.y * strideA;
    float* Cb = C + (long)blockIdx.y * strideC;
    int m0 = blockIdx.x * BM;
    int n0 = blockIdx.z * BM;
    int tid = threadIdx.x;
    int ty = tid >> 4, tx = tid & 15;

    ull acc[8][4];
#pragma unroll
    for (int n = 0; n < 8; n++)
#pragma unroll
        for (int m = 0; m < 4; m++) acc[n][m] = pk(0.f, 0.f);

    for (int kt = 0; kt < K; kt += BK) {
        // --- load A tile ---
        if (A_KMAJOR) {
#pragma unroll
            for (int r = 0; r < 2; r++) {
                int e = tid + r * 256;
                int k = e >> 5, m = (e & 31) * 4;
                float4 v = *(const float4*)(Ab + (long)(kt + k) * lda + m0 + m);
                *(float2*)&As[k * AS + m] = make_float2(v.x, v.y);
                *(float2*)&As[k * AS + m + 2] = make_float2(v.z, v.w);
            }
        } else {
#pragma unroll
            for (int r = 0; r < 2; r++) {
                int e = tid + r * 256;
                int m = e >> 2, k = (e & 3) * 4;
                float4 v = *(const float4*)(Ab + (long)(m0 + m) * lda + kt + k);
                As[(k + 0) * AS + m] = v.x;
                As[(k + 1) * AS + m] = v.y;
                As[(k + 2) * AS + m] = v.z;
                As[(k + 3) * AS + m] = v.w;
            }
        }
        // --- load B tile (transpose to Bs[k][n]) ---
#pragma unroll
        for (int r = 0; r < 2; r++) {
            int e = tid + r * 256;
            int n = e >> 2, k = (e & 3) * 4;
            float4 v = *(const float4*)(Bm + (long)(n0 + n) * K + kt + k);
            Bs[(k + 0) * AS + n] = v.x;
            Bs[(k + 1) * AS + n] = v.y;
            Bs[(k + 2) * AS + n] = v.z;
            Bs[(k + 3) * AS + n] = v.w;
        }
        __syncthreads();
#pragma unroll
        for (int k = 0; k < BK; k++) {
            ull a0 = *(ull*)&As[k * AS + ty * 4];
            ull a1 = *(ull*)&As[k * AS + ty * 4 + 2];
            ull a2 = *(ull*)&As[k * AS + 64 + ty * 4];
            ull a3 = *(ull*)&As[k * AS + 64 + ty * 4 + 2];
            float2 b01 = *(float2*)&Bs[k * AS + tx * 4];
            float2 b23 = *(float2*)&Bs[k * AS + tx * 4 + 2];
            float2 b45 = *(float2*)&Bs[k * AS + 64 + tx * 4];
            float2 b67 = *(float2*)&Bs[k * AS + 64 + tx * 4 + 2];
            float bn[8] = {b01.x, b01.y, b23.x, b23.y, b45.x, b45.y, b67.x, b67.y};
#pragma unroll
            for (int n = 0; n < 8; n++) {
                ull bb = pk(bn[n], bn[n]);
                acc[n][0] = fma2(a0, bb, acc[n][0]);
                acc[n][1] = fma2(a1, bb, acc[n][1]);
                acc[n][2] = fma2(a2, bb, acc[n][2]);
                acc[n][3] = fma2(a3, bb, acc[n][3]);
            }
        }
        __syncthreads();
    }

    // --- epilogue ---
    float cacc[8][8];
#pragma unroll
    for (int n = 0; n < 8; n++)
#pragma unroll
        for (int mp = 0; mp < 4; mp++)
            upk(acc[n][mp], cacc[n][2 * mp], cacc[n][2 * mp + 1]);

    float bv[8];
#pragma unroll
    for (int n = 0; n < 8; n++) {
        int col = (n < 4) ? (n0 + tx * 4 + n) : (n0 + 64 + tx * 4 + n - 4);
        bv[n] = bias ? bias[col] : 0.0f;
    }
#pragma unroll
    for (int mi = 0; mi < 8; mi++) {
        int m = (mi < 4) ? (ty * 4 + mi) : (64 + ty * 4 + mi - 4);
        float o[8];
#pragma unroll
        for (int n = 0; n < 8; n++) {
            float v = cacc[n][mi] + bv[n];
            o[n] = RELU ? fmaxf(v, 0.0f) : v;
        }
        *(float4*)&Cb[(long)(m0 + m) * ldc + n0 + tx * 4] = make_float4(o[0], o[1], o[2], o[3]);
        *(float4*)&Cb[(long)(m0 + m) * ldc + n0 + 64 + tx * 4] = make_float4(o[4], o[5], o[6], o[7]);
    }
}

// ---------------------------------------------------------------------------
// Block reduce (128 threads) for two values
// ---------------------------------------------------------------------------
__device__ __forceinline__ void block_reduce2(float& a, float& b) {
    __shared__ float sa[4], sb[4];
#pragma unroll
    for (int o = 16; o; o >>= 1) {
        a += __shfl_xor_sync(0xffffffffu, a, o);
        b += __shfl_xor_sync(0xffffffffu, b, o);
    }
    int w = threadIdx.x >> 5, l = threadIdx.x & 31;
    if (l == 0) { sa[w] = a; sb[w] = b; }
    __syncthreads();
    a = sa[0] + sa[1] + sa[2] + sa[3];
    b = sb[0] + sb[1] + sb[2] + sb[3];
}

// ---------------------------------------------------------------------------
// K4: GLU + bias + residual + LayerNorm1  -> g_xn
// ---------------------------------------------------------------------------
__global__ __launch_bounds__(128) void glu_ln1_kernel(
    const float* __restrict__ x, const float* __restrict__ b_out,
    const float* __restrict__ g1, const float* __restrict__ beta1) {
    long p = blockIdx.x;
    const float* zr = g_z + p * (2 * HH);
    const float* xr = x + p * HH;
    float r[4];
    float sum = 0.f, sumsq = 0.f;
#pragma unroll
    for (int j = 0; j < 4; j++) {
        int h = threadIdx.x + j * 128;
        float a = zr[h] + b_out[h];
        float g = zr[HH + h] + b_out[HH + h];
        float v = xr[h] + a * (1.0f / (1.0f + expf(-g)));
        r[j] = v;
        sum += v; sumsq += v * v;
    }
    block_reduce2(sum, sumsq);
    float mu = sum * (1.0f / HH);
    float var = sumsq * (1.0f / HH) - mu * mu;
    float rs = rsqrtf(var + 1e-5f);
    float* xo = g_xn + p * HH;
#pragma unroll
    for (int j = 0; j < 4; j++) {
        int h = threadIdx.x + j * 128;
        xo[h] = (r[j] - mu) * rs * g1[h] + beta1[h];
    }
}

// ---------------------------------------------------------------------------
// K7: residual + LayerNorm2 -> d_out
// ---------------------------------------------------------------------------
__global__ __launch_bounds__(128) void ln2_kernel(
    const float* __restrict__ g2, const float* __restrict__ beta2,
    float* __restrict__ out) {
    long p = blockIdx.x;
    const float* xr = g_xn + p * HH;
    const float* yr = g_y3 + p * HH;
    float r[4];
    float sum = 0.f, sumsq = 0.f;
#pragma unroll
    for (int j = 0; j < 4; j++) {
        int h = threadIdx.x + j * 128;
        float v = xr[h] + yr[h];
        r[j] = v;
        sum += v; sumsq += v * v;
    }
    block_reduce2(sum, sumsq);
    float mu = sum * (1.0f / HH);
    float var = sumsq * (1.0f / HH) - mu * mu;
    float rs = rsqrtf(var + 1e-5f);
    float* o = out + p * HH;
#pragma unroll
    for (int j = 0; j < 4; j++) {
        int h = threadIdx.x + j * 128;
        o[h] = (r[j] - mu) * rs * g2[h] + beta2[h];
    }
}

// ---------------------------------------------------------------------------
// Host launch
// ---------------------------------------------------------------------------
extern "C" void kernel_launch(void* const* d_in, const int* in_sizes, int n_in,
                              void* d_out, int out_size) {
    const float* x      = (const float*)d_in[0];
    const float* log_dt = (const float*)d_in[1];
    const float* A_re   = (const float*)d_in[2];
    const float* A_im   = (const float*)d_in[3];
    const float* C_re   = (const float*)d_in[4];
    const float* C_im   = (const float*)d_in[5];
    const float* D_skip = (const float*)d_in[6];
    const float* W_out  = (const float*)d_in[7];
    const float* b_out  = (const float*)d_in[8];
    const float* g1     = (const float*)d_in[9];
    const float* beta1  = (const float*)d_in[10];
    const float* g2     = (const float*)d_in[11];
    const float* beta2  = (const float*)d_in[12];
    const float* W1     = (const float*)d_in[13];
    const float* bc1    = (const float*)d_in[14];
    const float* W2     = (const float*)d_in[15];
    const float* bc2    = (const float*)d_in[16];
    float* out = (float*)d_out;

    float *p_yact, *p_z, *p_xn, *p_h1, *p_y3;
    cudaGetSymbolAddress((void**)&p_yact, g_yact);
    cudaGetSymbolAddress((void**)&p_z, g_z);
    cudaGetSymbolAddress((void**)&p_xn, g_xn);
    cudaGetSymbolAddress((void**)&p_h1, g_h1);
    cudaGetSymbolAddress((void**)&p_y3, g_y3);

    // K1: transpose x -> (B,H,L)
    transpose_kernel<<<dim3(LL / 32, HH / 32, BB), dim3(32, 8)>>>(x);

    // K2: scan
    scan_kernel<<<(BB * HH) / 4, 128>>>(log_dt, A_re, A_im, C_re, C_im, D_skip);

    // K3: GEMM1  z[p,f] = sum_h yact[h,p] * W_out[f,h]   (batched over b)
    sgemm_kernel<true, false><<<dim3(LL / 128, BB, (2 * HH) / 128), 256>>>(
        p_yact, W_out, b_out, p_z, HH, LL, 2 * HH,
        (long)HH * LL, (long)LL * 2 * HH);

    // K4: GLU + residual + LN1
    glu_ln1_kernel<<<PP, 128>>>(x, b_out, g1, beta1);

    // K5: GEMM2  h1 = relu(xn @ W1^T + bc1)
    sgemm_kernel<false, true><<<dim3(PP / 128, 1, HH / 128), 256>>>(
        p_xn, W1, bc1, p_h1, HH, HH, HH, 0, 0);

    // K6: GEMM3  y3 = h1 @ W2^T + bc2
    sgemm_kernel<false, false><<<dim3(PP / 128, 1, HH / 128), 256>>>(
        p_h1, W2, bc2, p_y3, HH, HH, HH, 0, 0);

    // K7: residual + LN2 -> out
    ln2_kernel<<<PP, 128>>>(g2, beta2, out);
}

// round 4
// speedup vs baseline: 1.7969x; 1.7969x over previous
#include <cuda_runtime.h>
#include <cuda_fp16.h>
#include <math.h>
#include <stdint.h>

typedef unsigned long long ull;

// ---------------------------------------------------------------------------
// Problem dims
// ---------------------------------------------------------------------------
#define BB 8
#define LL 2048
#define HH 512
#define NN 64
#define PP (BB * LL)          // 16384 tokens
#define K3 1536               // 3*HH hi/lo/hi concatenated K

// ---------------------------------------------------------------------------
// Scratch (device globals — no allocation allowed)
// ---------------------------------------------------------------------------
__device__ float g_xT[BB * HH * LL];          // x transposed (B,H,L)
__device__ float g_yact[BB * HH * LL];        // gelu(scan + D*u), (B,H,L)
__device__ __half g_Ac1[(long)PP * K3];       // GEMM1 A (hi,lo,hi)
__device__ __half g_Wc1[(long)1024 * K3];     // W_out (hi,hi,lo)
__device__ __half g_Wc2[(long)HH * K3];       // W1
__device__ __half g_Wc3[(long)HH * K3];       // W2
__device__ float g_z[(long)PP * 2 * HH];      // GEMM1 out (P, 1024)
__device__ float g_xn[(long)PP * HH];         // after GLU+res+LN1 (fp32)
__device__ __half g_xnc[(long)PP * K3];       // xn (hi,lo,hi) for GEMM2
__device__ __half g_h1c[(long)PP * K3];       // FFN hidden (hi,lo,hi) for GEMM3
__device__ float g_y3[(long)PP * HH];         // FFN out

// ---------------------------------------------------------------------------
// Packed f32x2 helpers (scan kernel)
// ---------------------------------------------------------------------------
__device__ __forceinline__ ull pk(float x, float y) {
    ull r; asm("mov.b64 %0, {%1,%2};" : "=l"(r) : "f"(x), "f"(y)); return r;
}
__device__ __forceinline__ void upk(ull v, float& x, float& y) {
    asm("mov.b64 {%0,%1}, %2;" : "=f"(x), "=f"(y) : "l"(v));
}
__device__ __forceinline__ ull fma2(ull a, ull b, ull c) {
    ull d; asm("fma.rn.f32x2 %0, %1, %2, %3;" : "=l"(d) : "l"(a), "l"(b), "l"(c)); return d;
}
__device__ __forceinline__ ull mul2(ull a, ull b) {
    ull d; asm("mul.rn.f32x2 %0, %1, %2;" : "=l"(d) : "l"(a), "l"(b)); return d;
}

// ---------------------------------------------------------------------------
// fp16 hi/lo split
// ---------------------------------------------------------------------------
__device__ __forceinline__ void hilo(float v, __half& h, __half& l) {
    h = __float2half_rn(v);
    l = __float2half_rn(v - __half2float(h));
}

// ---------------------------------------------------------------------------
// K1: transpose (B,L,H) -> (B,H,L)
// ---------------------------------------------------------------------------
__global__ __launch_bounds__(256) void transpose_kernel(const float* __restrict__ x) {
    __shared__ float t[32][33];
    int b = blockIdx.z;
    int l0 = blockIdx.x * 32;
    int h0 = blockIdx.y * 32;
    int tx = threadIdx.x, ty = threadIdx.y;  // 32 x 8
#pragma unroll
    for (int j = 0; j < 4; j++) {
        int l = l0 + ty + j * 8;
        t[ty + j * 8][tx] = x[((long)(b * LL + l)) * HH + h0 + tx];
    }
    __syncthreads();
#pragma unroll
    for (int j = 0; j < 4; j++) {
        int h = h0 + ty + j * 8;
        g_xT[((long)(b * HH + h)) * LL + l0 + tx] = t[tx][ty + j * 8];
    }
}

// ---------------------------------------------------------------------------
// K2: SSM scan + D-skip + gelu(tanh).  One warp per (b,h).
// ---------------------------------------------------------------------------
__global__ __launch_bounds__(128) void scan_kernel(
    const float* __restrict__ log_dt, const float* __restrict__ A_re,
    const float* __restrict__ A_im, const float* __restrict__ C_re,
    const float* __restrict__ C_im, const float* __restrict__ D_skip) {
    int warp = threadIdx.x >> 5, lane = threadIdx.x & 31;
    int wg = blockIdx.x * 4 + warp;
    int b = wg >> 9, h = wg & 511;

    __shared__ float us[4][32];
    __shared__ float P[4][32 * 33];
    float* Pw = P[warp];
    float* uw = us[warp];

    float dt = expf(log_dt[h]);
    float wr_[2], wi_[2], c2r_[2], c2i_[2];
#pragma unroll
    for (int s = 0; s < 2; s++) {
        int n = lane + 32 * s;
        float ar = A_re[h * NN + n], ai = A_im[h * NN + n];
        float dr = dt * ar, di = dt * ai;
        float e = expf(dr);
        float sn, cs; sincosf(di, &sn, &cs);
        float wre = e * cs, wim = e * sn;
        float inv = 1.0f / (ar * ar + ai * ai);
        float qr = ((wre - 1.0f) * ar + wim * ai) * inv;
        float qi = (wim * ar - (wre - 1.0f) * ai) * inv;
        float cr = C_re[h * NN + n], ci = C_im[h * NN + n];
        c2r_[s] = 2.0f * (cr * qr - ci * qi);
        c2i_[s] = 2.0f * (cr * qi + ci * qr);
        wr_[s] = wre; wi_[s] = wim;
    }
    ull Wre  = pk(wr_[0], wr_[1]);
    ull Wim  = pk(wi_[0], wi_[1]);
    ull nWim = pk(-wi_[0], -wi_[1]);
    ull C2r  = pk(c2r_[0], c2r_[1]);
    ull nC2i = pk(-c2i_[0], -c2i_[1]);
    ull sre = pk(0.f, 0.f), sim = pk(0.f, 0.f);
    float Dh = D_skip[h];

    const float* ub = g_xT + ((long)(b * HH + h)) * LL;
    float* yb = g_yact + ((long)(b * HH + h)) * LL;

    for (int l0 = 0; l0 < LL; l0 += 32) {
        float umine = ub[l0 + lane];
        uw[lane] = umine;
        __syncwarp();
#pragma unroll
        for (int t = 0; t < 32; t++) {
            float u = uw[t];
            ull up = pk(u, u);
            ull tre = fma2(nWim, sim, up);
            ull srn = fma2(Wre, sre, tre);
            ull tim = mul2(Wim, sre);
            sim = fma2(Wre, sim, tim);
            sre = srn;
            ull pp = mul2(C2r, sre);
            pp = fma2(nC2i, sim, pp);
            float px, py; upk(pp, px, py);
            Pw[t * 33 + lane] = px + py;
        }
        __syncwarp();
        float s0 = 0, s1 = 0, s2 = 0, s3 = 0;
#pragma unroll
        for (int i = 0; i < 32; i += 4) {
            s0 += Pw[lane * 33 + i];
            s1 += Pw[lane * 33 + i + 1];
            s2 += Pw[lane * 33 + i + 2];
            s3 += Pw[lane * 33 + i + 3];
        }
        float yv = (s0 + s1) + (s2 + s3) + Dh * umine;
        float t3 = yv * yv * yv;
        float g = 0.5f * yv * (1.0f + tanhf(0.7978845608028654f * (yv + 0.044715f * t3)));
        yb[l0 + lane] = g;
        __syncwarp();
    }
}

// ---------------------------------------------------------------------------
// K3: weight convert  W[F][512] fp32 -> Wc[F][1536] fp16 (hi, hi, lo)
// ---------------------------------------------------------------------------
__global__ __launch_bounds__(256) void wconv_kernel(const float* __restrict__ W,
                                                    __half* __restrict__ Wc) {
    int idx = blockIdx.x * 256 + threadIdx.x;
    int f = idx >> 9, k = idx & 511;
    float v = W[idx];
    __half h, l; hilo(v, h, l);
    long base = (long)f * K3 + k;
    Wc[base] = h; Wc[base + 512] = h; Wc[base + 1024] = l;
}

// ---------------------------------------------------------------------------
// K4: yact (B,H,L) fp32 -> Ac1[p=(b,l)][1536] fp16 (hi, lo, hi), transposed
// ---------------------------------------------------------------------------
__global__ __launch_bounds__(256) void tconv_kernel() {
    __shared__ float t[32][33];
    int b = blockIdx.z;
    int l0 = blockIdx.x * 32;
    int h0 = blockIdx.y * 32;
    int tx = threadIdx.x, ty = threadIdx.y;  // 32 x 8
#pragma unroll
    for (int j = 0; j < 4; j++)
        t[ty + 8 * j][tx] = g_yact[((long)(b * HH + h0 + ty + 8 * j)) * LL + l0 + tx];
    __syncthreads();
#pragma unroll
    for (int j = 0; j < 4; j++) {
        int l = ty + 8 * j;
        float v = t[tx][l];
        __half h, lo; hilo(v, h, lo);
        long p = (long)b * LL + l0 + l;
        long base = p * K3 + h0 + tx;
        g_Ac1[base] = h; g_Ac1[base + 512] = lo; g_Ac1[base + 1024] = h;
    }
}

// ---------------------------------------------------------------------------
// HMMA GEMM:  C[M,N] = A[M,1536] @ B[N,1536]^T  (fp16 in, fp32 accum)
// BM=BN=128, BK=64, 3-stage cp.async, SW128 swizzle, mma.sync m16n8k16.
// 8 warps: warp_m = wid&1 (64 rows), warp_n = wid>>1 (32 cols).
// EPI: 0 = fp32, 1 = fp32 + bias, 2 = fp16 hi/lo/hi + bias + relu
// ---------------------------------------------------------------------------
#define STG_SZ 32768            // 16KB A + 16KB B per stage
#define GSMEM  (3 * STG_SZ)     // 98304
#define KTILES (K3 / 64)        // 24

__device__ __forceinline__ void cp_async16(uint32_t dst, const void* src) {
    asm volatile("cp.async.cg.shared.global [%0], [%1], 16;" :: "r"(dst), "l"(src));
}
#define CP_COMMIT() asm volatile("cp.async.commit_group;" ::: "memory")
#define CP_WAIT1()  asm volatile("cp.async.wait_group 1;" ::: "memory")

__device__ __forceinline__ void ldsm4(uint32_t a, uint32_t& r0, uint32_t& r1,
                                      uint32_t& r2, uint32_t& r3) {
    asm volatile("ldmatrix.sync.aligned.m8n8.x4.shared.b16 {%0,%1,%2,%3}, [%4];"
                 : "=r"(r0), "=r"(r1), "=r"(r2), "=r"(r3) : "r"(a));
}
__device__ __forceinline__ void mma16816(float* c, const uint32_t* a, uint32_t b0, uint32_t b1) {
    asm volatile("mma.sync.aligned.m16n8k16.row.col.f32.f16.f16.f32 "
                 "{%0,%1,%2,%3},{%4,%5,%6,%7},{%8,%9},{%0,%1,%2,%3};"
                 : "+f"(c[0]), "+f"(c[1]), "+f"(c[2]), "+f"(c[3])
                 : "r"(a[0]), "r"(a[1]), "r"(a[2]), "r"(a[3]), "r"(b0), "r"(b1));
}

template <int EPI>
__global__ __launch_bounds__(256)
void mma_gemm(const __half* __restrict__ A, const __half* __restrict__ Bw,
              const float* __restrict__ bias, void* __restrict__ Cout, int ldc) {
    extern __shared__ char smem[];
    uint32_t sb = (uint32_t)__cvta_generic_to_shared(smem);
    int tid = threadIdx.x, wid = tid >> 5, lane = tid & 31;
    int wm = wid & 1, wn = wid >> 1;
    long m0 = (long)blockIdx.x * 128;
    long n0 = (long)blockIdx.y * 128;

    auto load_tile = [&](int t, int s) {
        long k0 = (long)t * 64;
        uint32_t Ad = sb + s * STG_SZ;
        uint32_t Bd = Ad + 16384;
        const char* Ag = (const char*)(A + m0 * K3 + k0);
        const char* Bg = (const char*)(Bw + n0 * K3 + k0);
#pragma unroll
        for (int i = 0; i < 4; i++) {
            int e = tid + i * 256;
            int r = e >> 3, c = e & 7;
            uint32_t off = r * 128 + ((c ^ (r & 7)) << 4);
            cp_async16(Ad + off, Ag + (long)r * (K3 * 2) + c * 16);
            cp_async16(Bd + off, Bg + (long)r * (K3 * 2) + c * 16);
        }
    };

    float acc[16][4];
#pragma unroll
    for (int i = 0; i < 16; i++)
#pragma unroll
        for (int j = 0; j < 4; j++) acc[i][j] = 0.0f;

    load_tile(0, 0); CP_COMMIT();
    load_tile(1, 1); CP_COMMIT();

    // per-thread ldmatrix source offsets (within a stage)
    int arow = wm * 64 + (lane & 15);
    int achk = lane >> 4;                               // 0/1 -> k chunk +0/+1
    int brow = wn * 32 + (lane & 7) + (((lane >> 4) & 1) << 3);
    int bchk = (lane >> 3) & 1;

    for (int t = 0; t < KTILES; t++) {
        CP_WAIT1();
        __syncthreads();
        int tn = t + 2;
        if (tn < KTILES) load_tile(tn, tn % 3);
        CP_COMMIT();

        uint32_t Ab = sb + (t % 3) * STG_SZ;
        uint32_t Bb = Ab + 16384;
#pragma unroll
        for (int ks = 0; ks < 4; ks++) {
            uint32_t af[4][4], bf[2][4];
#pragma unroll
            for (int mt = 0; mt < 4; mt++) {
                int r = arow + mt * 16;
                int c = 2 * ks + achk;
                ldsm4(Ab + r * 128 + ((c ^ (r & 7)) << 4),
                      af[mt][0], af[mt][1], af[mt][2], af[mt][3]);
            }
#pragma unroll
            for (int np = 0; np < 2; np++) {
                int r = brow + np * 16;
                int c = 2 * ks + bchk;
                ldsm4(Bb + r * 128 + ((c ^ (r & 7)) << 4),
                      bf[np][0], bf[np][1], bf[np][2], bf[np][3]);
            }
#pragma unroll
            for (int mt = 0; mt < 4; mt++)
#pragma unroll
                for (int nt = 0; nt < 4; nt++)
                    mma16816(acc[mt * 4 + nt], af[mt],
                             bf[nt >> 1][(nt & 1) * 2], bf[nt >> 1][(nt & 1) * 2 + 1]);
        }
        __syncthreads();
    }

    // ---- epilogue: regs -> gmem ----
    int rbase = (int)m0 + wm * 64 + (lane >> 2);
    int cbase = (int)n0 + wn * 32 + (lane & 3) * 2;
#pragma unroll
    for (int mt = 0; mt < 4; mt++) {
#pragma unroll
        for (int nt = 0; nt < 4; nt++) {
            float* d = acc[mt * 4 + nt];
            int col = cbase + nt * 8;
            int row0 = rbase + mt * 16, row1 = row0 + 8;
            if (EPI == 0) {
                float* C = (float*)Cout;
                *(float2*)&C[(long)row0 * ldc + col] = make_float2(d[0], d[1]);
                *(float2*)&C[(long)row1 * ldc + col] = make_float2(d[2], d[3]);
            } else if (EPI == 1) {
                float b0 = bias[col], b1 = bias[col + 1];
                float* C = (float*)Cout;
                *(float2*)&C[(long)row0 * ldc + col] = make_float2(d[0] + b0, d[1] + b1);
                *(float2*)&C[(long)row1 * ldc + col] = make_float2(d[2] + b0, d[3] + b1);
            } else {
                float b0 = bias[col], b1 = bias[col + 1];
                __half* C = (__half*)Cout;
                float v00 = fmaxf(d[0] + b0, 0.f), v01 = fmaxf(d[1] + b1, 0.f);
                float v10 = fmaxf(d[2] + b0, 0.f), v11 = fmaxf(d[3] + b1, 0.f);
                __half h00, l00, h01, l01, h10, l10, h11, l11;
                hilo(v00, h00, l00); hilo(v01, h01, l01);
                hilo(v10, h10, l10); hilo(v11, h11, l11);
                long base0 = (long)row0 * K3 + col;
                long base1 = (long)row1 * K3 + col;
                *(__half2*)&C[base0]        = __halves2half2(h00, h01);
                *(__half2*)&C[base0 + 512]  = __halves2half2(l00, l01);
                *(__half2*)&C[base0 + 1024] = __halves2half2(h00, h01);
                *(__half2*)&C[base1]        = __halves2half2(h10, h11);
                *(__half2*)&C[base1 + 512]  = __halves2half2(l10, l11);
                *(__half2*)&C[base1 + 1024] = __halves2half2(h10, h11);
            }
        }
    }
}

// ---------------------------------------------------------------------------
// Block reduce (128 threads) for two values
// ---------------------------------------------------------------------------
__device__ __forceinline__ void block_reduce2(float& a, float& b) {
    __shared__ float sa[4], sb2[4];
#pragma unroll
    for (int o = 16; o; o >>= 1) {
        a += __shfl_xor_sync(0xffffffffu, a, o);
        b += __shfl_xor_sync(0xffffffffu, b, o);
    }
    int w = threadIdx.x >> 5, l = threadIdx.x & 31;
    if (l == 0) { sa[w] = a; sb2[w] = b; }
    __syncthreads();
    a = sa[0] + sa[1] + sa[2] + sa[3];
    b = sb2[0] + sb2[1] + sb2[2] + sb2[3];
}

// ---------------------------------------------------------------------------
// K6: GLU + bias + residual + LayerNorm1 -> g_xn (fp32) + g_xnc (fp16 h/l/h)
// ---------------------------------------------------------------------------
__global__ __launch_bounds__(128) void glu_ln1_kernel(
    const float* __restrict__ x, const float* __restrict__ b_out,
    const float* __restrict__ g1, const float* __restrict__ beta1) {
    long p = blockIdx.x;
    const float* zr = g_z + p * (2 * HH);
    const float* xr = x + p * HH;
    float r[4];
    float sum = 0.f, sumsq = 0.f;
#pragma unroll
    for (int j = 0; j < 4; j++) {
        int h = threadIdx.x + j * 128;
        float a = zr[h] + b_out[h];
        float g = zr[HH + h] + b_out[HH + h];
        float v = xr[h] + a * (1.0f / (1.0f + expf(-g)));
        r[j] = v;
        sum += v; sumsq += v * v;
    }
    block_reduce2(sum, sumsq);
    float mu = sum * (1.0f / HH);
    float var = sumsq * (1.0f / HH) - mu * mu;
    float rs = rsqrtf(var + 1e-5f);
    float* xo = g_xn + p * HH;
    __half* xc = g_xnc + p * K3;
#pragma unroll
    for (int j = 0; j < 4; j++) {
        int h = threadIdx.x + j * 128;
        float v = (r[j] - mu) * rs * g1[h] + beta1[h];
        xo[h] = v;
        __half hh, ll; hilo(v, hh, ll);
        xc[h] = hh; xc[512 + h] = ll; xc[1024 + h] = hh;
    }
}

// ---------------------------------------------------------------------------
// K9: residual + LayerNorm2 -> d_out
// ---------------------------------------------------------------------------
__global__ __launch_bounds__(128) void ln2_kernel(
    const float* __restrict__ g2, const float* __restrict__ beta2,
    float* __restrict__ out) {
    long p = blockIdx.x;
    const float* xr = g_xn + p * HH;
    const float* yr = g_y3 + p * HH;
    float r[4];
    float sum = 0.f, sumsq = 0.f;
#pragma unroll
    for (int j = 0; j < 4; j++) {
        int h = threadIdx.x + j * 128;
        float v = xr[h] + yr[h];
        r[j] = v;
        sum += v; sumsq += v * v;
    }
    block_reduce2(sum, sumsq);
    float mu = sum * (1.0f / HH);
    float var = sumsq * (1.0f / HH) - mu * mu;
    float rs = rsqrtf(var + 1e-5f);
    float* o = out + p * HH;
#pragma unroll
    for (int j = 0; j < 4; j++) {
        int h = threadIdx.x + j * 128;
        o[h] = (r[j] - mu) * rs * g2[h] + beta2[h];
    }
}

// ---------------------------------------------------------------------------
// Host launch
// ---------------------------------------------------------------------------
extern "C" void kernel_launch(void* const* d_in, const int* in_sizes, int n_in,
                              void* d_out, int out_size) {
    const float* x      = (const float*)d_in[0];
    const float* log_dt = (const float*)d_in[1];
    const float* A_re   = (const float*)d_in[2];
    const float* A_im   = (const float*)d_in[3];
    const float* C_re   = (const float*)d_in[4];
    const float* C_im   = (const float*)d_in[5];
    const float* D_skip = (const float*)d_in[6];
    const float* W_out  = (const float*)d_in[7];
    const float* b_out  = (const float*)d_in[8];
    const float* g1     = (const float*)d_in[9];
    const float* beta1  = (const float*)d_in[10];
    const float* g2     = (const float*)d_in[11];
    const float* beta2  = (const float*)d_in[12];
    const float* W1     = (const float*)d_in[13];
    const float* bc1    = (const float*)d_in[14];
    const float* W2     = (const float*)d_in[15];
    const float* bc2    = (const float*)d_in[16];
    float* out = (float*)d_out;

    __half *p_Ac1, *p_Wc1, *p_Wc2, *p_Wc3, *p_xnc, *p_h1c;
    float *p_z, *p_y3;
    cudaGetSymbolAddress((void**)&p_Ac1, g_Ac1);
    cudaGetSymbolAddress((void**)&p_Wc1, g_Wc1);
    cudaGetSymbolAddress((void**)&p_Wc2, g_Wc2);
    cudaGetSymbolAddress((void**)&p_Wc3, g_Wc3);
    cudaGetSymbolAddress((void**)&p_xnc, g_xnc);
    cudaGetSymbolAddress((void**)&p_h1c, g_h1c);
    cudaGetSymbolAddress((void**)&p_z, g_z);
    cudaGetSymbolAddress((void**)&p_y3, g_y3);

    cudaFuncSetAttribute(mma_gemm<0>, cudaFuncAttributeMaxDynamicSharedMemorySize, GSMEM);
    cudaFuncSetAttribute(mma_gemm<1>, cudaFuncAttributeMaxDynamicSharedMemorySize, GSMEM);
    cudaFuncSetAttribute(mma_gemm<2>, cudaFuncAttributeMaxDynamicSharedMemorySize, GSMEM);

    // K1: transpose x -> (B,H,L)
    transpose_kernel<<<dim3(LL / 32, HH / 32, BB), dim3(32, 8)>>>(x);

    // K2: scan -> g_yact
    scan_kernel<<<(BB * HH) / 4, 128>>>(log_dt, A_re, A_im, C_re, C_im, D_skip);

    // K3: weight conversions
    wconv_kernel<<<(1024 * 512) / 256, 256>>>(W_out, p_Wc1);
    wconv_kernel<<<(512 * 512) / 256, 256>>>(W1, p_Wc2);
    wconv_kernel<<<(512 * 512) / 256, 256>>>(W2, p_Wc3);

    // K4: yact -> Ac1 (transpose + hi/lo/hi)
    tconv_kernel<<<dim3(LL / 32, HH / 32, BB), dim3(32, 8)>>>();

    // K5: GEMM1  z = Ac1 @ Wc1^T   (M=16384, N=1024)
    mma_gemm<0><<<dim3(PP / 128, 1024 / 128), 256, GSMEM>>>(p_Ac1, p_Wc1, nullptr, p_z, 1024);

    // K6: GLU + residual + LN1 -> g_xn, g_xnc
    glu_ln1_kernel<<<PP, 128>>>(x, b_out, g1, beta1);

    // K7: GEMM2  h1c = relu(xn @ W1^T + bc1) as fp16 hi/lo/hi  (N=512)
    mma_gemm<2><<<dim3(PP / 128, 512 / 128), 256, GSMEM>>>(p_xnc, p_Wc2, bc1, p_h1c, 0);

    // K8: GEMM3  y3 = h1 @ W2^T + bc2  (N=512)
    mma_gemm<1><<<dim3(PP / 128, 512 / 128), 256, GSMEM>>>(p_h1c, p_Wc3, bc2, p_y3, 512);

    // K9: residual + LN2 -> out
    ln2_kernel<<<PP, 128>>>(g2, beta2, out);
}

// round 5
// speedup vs baseline: 1.8632x; 1.0369x over previous
#include <cuda_runtime.h>
#include <cuda_fp16.h>
#include <math.h>
#include <stdint.h>

typedef unsigned long long ull;

// ---------------------------------------------------------------------------
// Problem dims
// ---------------------------------------------------------------------------
#define BB 8
#define LL 2048
#define HH 512
#define NN 64
#define PP (BB * LL)          // 16384 tokens
#define K3 1536               // 3*HH hi/lo/hi concatenated K

// ---------------------------------------------------------------------------
// Scratch (device globals — no allocation allowed)
// ---------------------------------------------------------------------------
__device__ __half2 g_yh[(long)BB * HH * LL];  // gelu(scan+D*u) as (hi,lo), (B,H,L)
__device__ __half g_Ac1[(long)PP * K3];       // GEMM1 A (hi,lo,hi)
__device__ __half g_Wc1[(long)1024 * K3];     // W_out permuted (hi,hi,lo)
__device__ __half g_Wc2[(long)HH * K3];       // W1
__device__ __half g_Wc3[(long)HH * K3];       // W2
__device__ float g_glu[(long)PP * HH];        // GEMM1+GLU out (P, 512)
__device__ float g_xn[(long)PP * HH];         // after res+LN1 (fp32)
__device__ __half g_xnc[(long)PP * K3];       // xn (hi,lo,hi) for GEMM2
__device__ __half g_h1c[(long)PP * K3];       // FFN hidden (hi,lo,hi) for GEMM3
__device__ float g_y3[(long)PP * HH];         // FFN out

// ---------------------------------------------------------------------------
// Packed f32x2 helpers
// ---------------------------------------------------------------------------
__device__ __forceinline__ ull pk(float x, float y) {
    ull r; asm("mov.b64 %0, {%1,%2};" : "=l"(r) : "f"(x), "f"(y)); return r;
}
__device__ __forceinline__ void upk(ull v, float& x, float& y) {
    asm("mov.b64 {%0,%1}, %2;" : "=f"(x), "=f"(y) : "l"(v));
}
__device__ __forceinline__ ull fma2(ull a, ull b, ull c) {
    ull d; asm("fma.rn.f32x2 %0, %1, %2, %3;" : "=l"(d) : "l"(a), "l"(b), "l"(c)); return d;
}
__device__ __forceinline__ ull mul2(ull a, ull b) {
    ull d; asm("mul.rn.f32x2 %0, %1, %2;" : "=l"(d) : "l"(a), "l"(b)); return d;
}
__device__ __forceinline__ ull add2(ull a, ull b) {
    ull d; asm("add.rn.f32x2 %0, %1, %2;" : "=l"(d) : "l"(a), "l"(b)); return d;
}

// ---------------------------------------------------------------------------
// fp16 hi/lo split
// ---------------------------------------------------------------------------
__device__ __forceinline__ void hilo(float v, __half& h, __half& l) {
    h = __float2half_rn(v);
    l = __float2half_rn(v - __half2float(h));
}

// ---------------------------------------------------------------------------
// K1: SSM scan + D-skip + gelu(tanh), reads x (B,L,H) directly.
// Block = (b, h0..h0+3), one warp per h. Writes (hi,lo) fp16 pairs (B,H,L).
// ---------------------------------------------------------------------------
__global__ __launch_bounds__(128) void scan_kernel(
    const float* __restrict__ x,
    const float* __restrict__ log_dt, const float* __restrict__ A_re,
    const float* __restrict__ A_im, const float* __restrict__ C_re,
    const float* __restrict__ C_im, const float* __restrict__ D_skip) {
    int warp = threadIdx.x >> 5, lane = threadIdx.x & 31;
    int b = blockIdx.x >> 7;
    int h0 = (blockIdx.x & 127) * 4;
    int h = h0 + warp;

    __shared__ ull us[4][32];
    __shared__ float P[4][32 * 36];
    float* Pw = P[warp];
    ull* uw = us[warp];

    float dt = expf(log_dt[h]);
    float wr_[2], wi_[2], c2r_[2], c2i_[2];
#pragma unroll
    for (int s = 0; s < 2; s++) {
        int n = lane + 32 * s;
        float ar = A_re[h * NN + n], ai = A_im[h * NN + n];
        float dr = dt * ar, di = dt * ai;
        float e = expf(dr);
        float sn, cs; sincosf(di, &sn, &cs);
        float wre = e * cs, wim = e * sn;
        float inv = 1.0f / (ar * ar + ai * ai);
        float qr = ((wre - 1.0f) * ar + wim * ai) * inv;
        float qi = (wim * ar - (wre - 1.0f) * ai) * inv;
        float cr = C_re[h * NN + n], ci = C_im[h * NN + n];
        c2r_[s] = 2.0f * (cr * qr - ci * qi);
        c2i_[s] = 2.0f * (cr * qi + ci * qr);
        wr_[s] = wre; wi_[s] = wim;
    }
    ull Wre  = pk(wr_[0], wr_[1]);
    ull Wim  = pk(wi_[0], wi_[1]);
    ull nWim = pk(-wi_[0], -wi_[1]);
    ull C2r  = pk(c2r_[0], c2r_[1]);
    ull nC2i = pk(-c2i_[0], -c2i_[1]);
    ull sre = pk(0.f, 0.f), sim = pk(0.f, 0.f);
    float Dh = D_skip[h];

    const float* xb = x + ((long)b * LL) * HH + h0;
    __half2* yb = g_yh + ((long)(b * HH + h)) * LL;

    for (int l0 = 0; l0 < LL; l0 += 32) {
        // all 4 warps load identical lines; each keeps its own h component
        float4 v = *(const float4*)(xb + (long)(l0 + lane) * HH);
        float umine = (warp == 0) ? v.x : (warp == 1) ? v.y : (warp == 2) ? v.z : v.w;
        uw[lane] = pk(umine, umine);
        __syncwarp();
#pragma unroll
        for (int t = 0; t < 32; t++) {
            ull up = uw[t];
            ull tre = fma2(nWim, sim, up);
            ull srn = fma2(Wre, sre, tre);
            ull tim = mul2(Wim, sre);
            sim = fma2(Wre, sim, tim);
            sre = srn;
            ull pp = mul2(C2r, sre);
            pp = fma2(nC2i, sim, pp);
            float px, py; upk(pp, px, py);
            Pw[t * 36 + lane] = px + py;
        }
        __syncwarp();
        // packed reduction over this lane's row
        const ull* row = (const ull*)&Pw[lane * 36];
        ull a0 = row[0], a1 = row[1];
#pragma unroll
        for (int i = 2; i < 16; i += 2) {
            a0 = add2(a0, row[i]);
            a1 = add2(a1, row[i + 1]);
        }
        a0 = add2(a0, a1);
        float ax, ay; upk(a0, ax, ay);
        float yv = ax + ay + Dh * umine;
        float t3 = yv * yv * yv;
        float g = 0.5f * yv * (1.0f + tanhf(0.7978845608028654f * (yv + 0.044715f * t3)));
        __half hi, lo; hilo(g, hi, lo);
        yb[l0 + lane] = __halves2half2(hi, lo);
        __syncwarp();
    }
}

// ---------------------------------------------------------------------------
// K2: g_yh (B,H,L) half2 -> Ac1[p=(b,l)][1536] fp16 (hi, lo, hi), transposed
// ---------------------------------------------------------------------------
__global__ __launch_bounds__(256) void tconv_kernel() {
    __shared__ uint32_t t[32][33];
    int b = blockIdx.z;
    int l0 = blockIdx.x * 32;
    int h0 = blockIdx.y * 32;
    int tx = threadIdx.x, ty = threadIdx.y;  // 32 x 8
    const uint32_t* Y = (const uint32_t*)g_yh;
#pragma unroll
    for (int j = 0; j < 4; j++)
        t[ty + 8 * j][tx] = Y[((long)(b * HH + h0 + ty + 8 * j)) * LL + l0 + tx];
    __syncthreads();
#pragma unroll
    for (int j = 0; j < 4; j++) {
        int l = ty + 8 * j;
        __half2 v = *(__half2*)&t[tx][l];
        long p = (long)b * LL + l0 + l;
        long base = p * K3 + h0 + tx;
        g_Ac1[base] = __low2half(v);
        g_Ac1[base + 512] = __high2half(v);
        g_Ac1[base + 1024] = __low2half(v);
    }
}

// ---------------------------------------------------------------------------
// K3: weight convert  W[F][512] fp32 -> Wc[F or p(F)][1536] fp16 (hi, hi, lo)
// PERM: 0 = identity rows, 1 = GLU-interleave p(f) = (f&511)*2 + (f>>9)
// ---------------------------------------------------------------------------
template <int PERM>
__global__ __launch_bounds__(256) void wconv_kernel(const float* __restrict__ W,
                                                    __half* __restrict__ Wc) {
    int idx = blockIdx.x * 256 + threadIdx.x;
    int f = idx >> 9, k = idx & 511;
    float v = W[idx];
    __half h, l; hilo(v, h, l);
    int fo = PERM ? ((f & 511) * 2 + (f >> 9)) : f;
    long base = (long)fo * K3 + k;
    Wc[base] = h; Wc[base + 512] = h; Wc[base + 1024] = l;
}

// ---------------------------------------------------------------------------
// HMMA GEMM:  C[M,N] = A[M,1536] @ B[N,1536]^T  (fp16 in, fp32 accum)
// BM=BN=128, BK=64, 3-stage cp.async, SW128 swizzle, mma.sync m16n8k16.
// EPI: 1 = fp32 + bias, 2 = fp16 hi/lo/hi + bias + relu, 3 = GLU (paired cols)
// ---------------------------------------------------------------------------
#define STG_SZ 32768            // 16KB A + 16KB B per stage
#define GSMEM  (3 * STG_SZ)     // 98304
#define KTILES (K3 / 64)        // 24

__device__ __forceinline__ void cp_async16(uint32_t dst, const void* src) {
    asm volatile("cp.async.cg.shared.global [%0], [%1], 16;" :: "r"(dst), "l"(src));
}
#define CP_COMMIT() asm volatile("cp.async.commit_group;" ::: "memory")
#define CP_WAIT1()  asm volatile("cp.async.wait_group 1;" ::: "memory")

__device__ __forceinline__ void ldsm4(uint32_t a, uint32_t& r0, uint32_t& r1,
                                      uint32_t& r2, uint32_t& r3) {
    asm volatile("ldmatrix.sync.aligned.m8n8.x4.shared.b16 {%0,%1,%2,%3}, [%4];"
                 : "=r"(r0), "=r"(r1), "=r"(r2), "=r"(r3) : "r"(a));
}
__device__ __forceinline__ void mma16816(float* c, const uint32_t* a, uint32_t b0, uint32_t b1) {
    asm volatile("mma.sync.aligned.m16n8k16.row.col.f32.f16.f16.f32 "
                 "{%0,%1,%2,%3},{%4,%5,%6,%7},{%8,%9},{%0,%1,%2,%3};"
                 : "+f"(c[0]), "+f"(c[1]), "+f"(c[2]), "+f"(c[3])
                 : "r"(a[0]), "r"(a[1]), "r"(a[2]), "r"(a[3]), "r"(b0), "r"(b1));
}

template <int EPI>
__global__ __launch_bounds__(256)
void mma_gemm(const __half* __restrict__ A, const __half* __restrict__ Bw,
              const float* __restrict__ bias, void* __restrict__ Cout, int ldc) {
    extern __shared__ char smem[];
    uint32_t sb = (uint32_t)__cvta_generic_to_shared(smem);
    int tid = threadIdx.x, wid = tid >> 5, lane = tid & 31;
    int wm = wid & 1, wn = wid >> 1;
    long m0 = (long)blockIdx.x * 128;
    long n0 = (long)blockIdx.y * 128;

    auto load_tile = [&](int t, int s) {
        long k0 = (long)t * 64;
        uint32_t Ad = sb + s * STG_SZ;
        uint32_t Bd = Ad + 16384;
        const char* Ag = (const char*)(A + m0 * K3 + k0);
        const char* Bg = (const char*)(Bw + n0 * K3 + k0);
#pragma unroll
        for (int i = 0; i < 4; i++) {
            int e = tid + i * 256;
            int r = e >> 3, c = e & 7;
            uint32_t off = r * 128 + ((c ^ (r & 7)) << 4);
            cp_async16(Ad + off, Ag + (long)r * (K3 * 2) + c * 16);
            cp_async16(Bd + off, Bg + (long)r * (K3 * 2) + c * 16);
        }
    };

    float acc[16][4];
#pragma unroll
    for (int i = 0; i < 16; i++)
#pragma unroll
        for (int j = 0; j < 4; j++) acc[i][j] = 0.0f;

    load_tile(0, 0); CP_COMMIT();
    load_tile(1, 1); CP_COMMIT();

    int arow = wm * 64 + (lane & 15);
    int achk = lane >> 4;
    int brow = wn * 32 + (lane & 7) + (((lane >> 4) & 1) << 3);
    int bchk = (lane >> 3) & 1;

    for (int t = 0; t < KTILES; t++) {
        CP_WAIT1();
        __syncthreads();
        int tn = t + 2;
        if (tn < KTILES) load_tile(tn, tn % 3);
        CP_COMMIT();

        uint32_t Ab = sb + (t % 3) * STG_SZ;
        uint32_t Bb = Ab + 16384;
#pragma unroll
        for (int ks = 0; ks < 4; ks++) {
            uint32_t af[4][4], bf[2][4];
#pragma unroll
            for (int mt = 0; mt < 4; mt++) {
                int r = arow + mt * 16;
                int c = 2 * ks + achk;
                ldsm4(Ab + r * 128 + ((c ^ (r & 7)) << 4),
                      af[mt][0], af[mt][1], af[mt][2], af[mt][3]);
            }
#pragma unroll
            for (int np = 0; np < 2; np++) {
                int r = brow + np * 16;
                int c = 2 * ks + bchk;
                ldsm4(Bb + r * 128 + ((c ^ (r & 7)) << 4),
                      bf[np][0], bf[np][1], bf[np][2], bf[np][3]);
            }
#pragma unroll
            for (int mt = 0; mt < 4; mt++)
#pragma unroll
                for (int nt = 0; nt < 4; nt++)
                    mma16816(acc[mt * 4 + nt], af[mt],
                             bf[nt >> 1][(nt & 1) * 2], bf[nt >> 1][(nt & 1) * 2 + 1]);
        }
        __syncthreads();
    }

    // ---- epilogue ----
    int rbase = (int)m0 + wm * 64 + (lane >> 2);
    int cbase = (int)n0 + wn * 32 + (lane & 3) * 2;
#pragma unroll
    for (int mt = 0; mt < 4; mt++) {
#pragma unroll
        for (int nt = 0; nt < 4; nt++) {
            float* d = acc[mt * 4 + nt];
            int col = cbase + nt * 8;
            int row0 = rbase + mt * 16, row1 = row0 + 8;
            if (EPI == 1) {
                float b0 = bias[col], b1 = bias[col + 1];
                float* C = (float*)Cout;
                *(float2*)&C[(long)row0 * ldc + col] = make_float2(d[0] + b0, d[1] + b1);
                *(float2*)&C[(long)row1 * ldc + col] = make_float2(d[2] + b0, d[3] + b1);
            } else if (EPI == 2) {
                float b0 = bias[col], b1 = bias[col + 1];
                __half* C = (__half*)Cout;
                float v00 = fmaxf(d[0] + b0, 0.f), v01 = fmaxf(d[1] + b1, 0.f);
                float v10 = fmaxf(d[2] + b0, 0.f), v11 = fmaxf(d[3] + b1, 0.f);
                __half h00, l00, h01, l01, h10, l10, h11, l11;
                hilo(v00, h00, l00); hilo(v01, h01, l01);
                hilo(v10, h10, l10); hilo(v11, h11, l11);
                long base0 = (long)row0 * K3 + col;
                long base1 = (long)row1 * K3 + col;
                *(__half2*)&C[base0]        = __halves2half2(h00, h01);
                *(__half2*)&C[base0 + 512]  = __halves2half2(l00, l01);
                *(__half2*)&C[base0 + 1024] = __halves2half2(h00, h01);
                *(__half2*)&C[base1]        = __halves2half2(h10, h11);
                *(__half2*)&C[base1 + 512]  = __halves2half2(l10, l11);
                *(__half2*)&C[base1 + 1024] = __halves2half2(h10, h11);
            } else {
                // EPI==3: paired cols = (a_h, g_h); glu = a * sigmoid(g)
                int h = col >> 1;
                float ba = bias[h], bg = bias[512 + h];
                float a0 = d[0] + ba, gg0 = d[1] + bg;
                float a1 = d[2] + ba, gg1 = d[3] + bg;
                float v0 = a0 * (1.0f / (1.0f + expf(-gg0)));
                float v1 = a1 * (1.0f / (1.0f + expf(-gg1)));
                float* C = (float*)Cout;
                C[(long)row0 * HH + h] = v0;
                C[(long)row1 * HH + h] = v1;
            }
        }
    }
}

// ---------------------------------------------------------------------------
// Block reduce (128 threads) for two values
// ---------------------------------------------------------------------------
__device__ __forceinline__ void block_reduce2(float& a, float& b) {
    __shared__ float sa[4], sb2[4];
#pragma unroll
    for (int o = 16; o; o >>= 1) {
        a += __shfl_xor_sync(0xffffffffu, a, o);
        b += __shfl_xor_sync(0xffffffffu, b, o);
    }
    int w = threadIdx.x >> 5, l = threadIdx.x & 31;
    if (l == 0) { sa[w] = a; sb2[w] = b; }
    __syncthreads();
    a = sa[0] + sa[1] + sa[2] + sa[3];
    b = sb2[0] + sb2[1] + sb2[2] + sb2[3];
}

// ---------------------------------------------------------------------------
// K5: residual + LayerNorm1 -> g_xn (fp32) + g_xnc (fp16 h/l/h)
// ---------------------------------------------------------------------------
__global__ __launch_bounds__(128) void res_ln1_kernel(
    const float* __restrict__ x, const float* __restrict__ g1,
    const float* __restrict__ beta1) {
    long p = blockIdx.x;
    const float* gr = g_glu + p * HH;
    const float* xr = x + p * HH;
    float r[4];
    float sum = 0.f, sumsq = 0.f;
#pragma unroll
    for (int j = 0; j < 4; j++) {
        int h = threadIdx.x + j * 128;
        float v = xr[h] + gr[h];
        r[j] = v;
        sum += v; sumsq += v * v;
    }
    block_reduce2(sum, sumsq);
    float mu = sum * (1.0f / HH);
    float var = sumsq * (1.0f / HH) - mu * mu;
    float rs = rsqrtf(var + 1e-5f);
    float* xo = g_xn + p * HH;
    __half* xc = g_xnc + p * K3;
#pragma unroll
    for (int j = 0; j < 4; j++) {
        int h = threadIdx.x + j * 128;
        float v = (r[j] - mu) * rs * g1[h] + beta1[h];
        xo[h] = v;
        __half hh, ll; hilo(v, hh, ll);
        xc[h] = hh; xc[512 + h] = ll; xc[1024 + h] = hh;
    }
}

// ---------------------------------------------------------------------------
// K8: residual + LayerNorm2 -> d_out
// ---------------------------------------------------------------------------
__global__ __launch_bounds__(128) void ln2_kernel(
    const float* __restrict__ g2, const float* __restrict__ beta2,
    float* __restrict__ out) {
    long p = blockIdx.x;
    const float* xr = g_xn + p * HH;
    const float* yr = g_y3 + p * HH;
    float r[4];
    float sum = 0.f, sumsq = 0.f;
#pragma unroll
    for (int j = 0; j < 4; j++) {
        int h = threadIdx.x + j * 128;
        float v = xr[h] + yr[h];
        r[j] = v;
        sum += v; sumsq += v * v;
    }
    block_reduce2(sum, sumsq);
    float mu = sum * (1.0f / HH);
    float var = sumsq * (1.0f / HH) - mu * mu;
    float rs = rsqrtf(var + 1e-5f);
    float* o = out + p * HH;
#pragma unroll
    for (int j = 0; j < 4; j++) {
        int h = threadIdx.x + j * 128;
        o[h] = (r[j] - mu) * rs * g2[h] + beta2[h];
    }
}

// ---------------------------------------------------------------------------
// Host launch
// ---------------------------------------------------------------------------
extern "C" void kernel_launch(void* const* d_in, const int* in_sizes, int n_in,
                              void* d_out, int out_size) {
    const float* x      = (const float*)d_in[0];
    const float* log_dt = (const float*)d_in[1];
    const float* A_re   = (const float*)d_in[2];
    const float* A_im   = (const float*)d_in[3];
    const float* C_re   = (const float*)d_in[4];
    const float* C_im   = (const float*)d_in[5];
    const float* D_skip = (const float*)d_in[6];
    const float* W_out  = (const float*)d_in[7];
    const float* b_out  = (const float*)d_in[8];
    const float* g1     = (const float*)d_in[9];
    const float* beta1  = (const float*)d_in[10];
    const float* g2     = (const float*)d_in[11];
    const float* beta2  = (const float*)d_in[12];
    const float* W1     = (const float*)d_in[13];
    const float* bc1    = (const float*)d_in[14];
    const float* W2     = (const float*)d_in[15];
    const float* bc2    = (const float*)d_in[16];
    float* out = (float*)d_out;

    __half *p_Ac1, *p_Wc1, *p_Wc2, *p_Wc3, *p_xnc, *p_h1c;
    float *p_glu, *p_y3;
    cudaGetSymbolAddress((void**)&p_Ac1, g_Ac1);
    cudaGetSymbolAddress((void**)&p_Wc1, g_Wc1);
    cudaGetSymbolAddress((void**)&p_Wc2, g_Wc2);
    cudaGetSymbolAddress((void**)&p_Wc3, g_Wc3);
    cudaGetSymbolAddress((void**)&p_xnc, g_xnc);
    cudaGetSymbolAddress((void**)&p_h1c, g_h1c);
    cudaGetSymbolAddress((void**)&p_glu, g_glu);
    cudaGetSymbolAddress((void**)&p_y3, g_y3);

    cudaFuncSetAttribute(mma_gemm<1>, cudaFuncAttributeMaxDynamicSharedMemorySize, GSMEM);
    cudaFuncSetAttribute(mma_gemm<2>, cudaFuncAttributeMaxDynamicSharedMemorySize, GSMEM);
    cudaFuncSetAttribute(mma_gemm<3>, cudaFuncAttributeMaxDynamicSharedMemorySize, GSMEM);

    // 1) scan (reads x directly) -> g_yh
    scan_kernel<<<BB * HH / 4, 128>>>(x, log_dt, A_re, A_im, C_re, C_im, D_skip);

    // 2) yh -> Ac1 (transpose + hi/lo/hi)
    tconv_kernel<<<dim3(LL / 32, HH / 32, BB), dim3(32, 8)>>>();

    // 3) W_out permuted conversion
    wconv_kernel<1><<<(1024 * 512) / 256, 256>>>(W_out, p_Wc1);

    // 4) GEMM1 + fused GLU  -> g_glu  (N=1024 interleaved a/g)   [profiled slot]
    mma_gemm<3><<<dim3(PP / 128, 1024 / 128), 256, GSMEM>>>(p_Ac1, p_Wc1, b_out, p_glu, 0);

    // 5) W1 conversion
    wconv_kernel<0><<<(512 * 512) / 256, 256>>>(W1, p_Wc2);

    // 6) residual + LN1 -> g_xn, g_xnc
    res_ln1_kernel<<<PP, 128>>>(x, g1, beta1);

    // 7) GEMM2  h1c = relu(xn @ W1^T + bc1) as fp16 hi/lo/hi
    mma_gemm<2><<<dim3(PP / 128, 512 / 128), 256, GSMEM>>>(p_xnc, p_Wc2, bc1, p_h1c, 0);

    // 8) W2 conversion
    wconv_kernel<0><<<(512 * 512) / 256, 256>>>(W2, p_Wc3);

    // 9) GEMM3  y3 = h1 @ W2^T + bc2
    mma_gemm<1><<<dim3(PP / 128, 512 / 128), 256, GSMEM>>>(p_h1c, p_Wc3, bc2, p_y3, 512);

    // 10) residual + LN2 -> out
    ln2_kernel<<<PP, 128>>>(g2, beta2, out);
}

// round 8
// speedup vs baseline: 1.9036x; 1.0217x over previous
#include <cuda_runtime.h>
#include <cuda_fp16.h>
#include <math.h>
#include <stdint.h>

typedef unsigned long long ull;

// ---------------------------------------------------------------------------
// Problem dims
// ---------------------------------------------------------------------------
#define BB 8
#define LL 2048
#define HH 512
#define NN 64
#define PP (BB * LL)          // 16384 tokens
#define KK 1024               // 2*HH hi/lo concatenated K (2-term split)

// ---------------------------------------------------------------------------
// Scratch (device globals — no allocation allowed)
// ---------------------------------------------------------------------------
__device__ __half2 g_yh[(long)BB * HH * LL];  // gelu(scan+D*u) as (hi,lo), (B,H,L)
__device__ __half g_Ac1[(long)PP * KK];       // GEMM1 A (hi,lo)
__device__ __half g_Wc1[(long)1024 * KK];     // W_out permuted (hi,hi)
__device__ __half g_Wc2[(long)HH * KK];       // W1
__device__ __half g_Wc3[(long)HH * KK];       // W2
__device__ float g_glu[(long)PP * HH];        // GEMM1+GLU out (P, 512)
__device__ float g_xn[(long)PP * HH];         // after res+LN1 (fp32)
__device__ __half g_xnc[(long)PP * KK];       // xn (hi,lo) for GEMM2
__device__ __half g_h1c[(long)PP * KK];       // FFN hidden (hi,lo) for GEMM3
__device__ float g_y3[(long)PP * HH];         // FFN out

// ---------------------------------------------------------------------------
// Packed f32x2 helpers
// ---------------------------------------------------------------------------
__device__ __forceinline__ ull pk(float x, float y) {
    ull r; asm("mov.b64 %0, {%1,%2};" : "=l"(r) : "f"(x), "f"(y)); return r;
}
__device__ __forceinline__ void upk(ull v, float& x, float& y) {
    asm("mov.b64 {%0,%1}, %2;" : "=f"(x), "=f"(y) : "l"(v));
}
__device__ __forceinline__ ull fma2(ull a, ull b, ull c) {
    ull d; asm("fma.rn.f32x2 %0, %1, %2, %3;" : "=l"(d) : "l"(a), "l"(b), "l"(c)); return d;
}
__device__ __forceinline__ ull mul2(ull a, ull b) {
    ull d; asm("mul.rn.f32x2 %0, %1, %2;" : "=l"(d) : "l"(a), "l"(b)); return d;
}
__device__ __forceinline__ ull add2(ull a, ull b) {
    ull d; asm("add.rn.f32x2 %0, %1, %2;" : "=l"(d) : "l"(a), "l"(b)); return d;
}

// ---------------------------------------------------------------------------
// fp16 hi/lo split
// ---------------------------------------------------------------------------
__device__ __forceinline__ void hilo(float v, __half& h, __half& l) {
    h = __float2half_rn(v);
    l = __float2half_rn(v - __half2float(h));
}

// ---------------------------------------------------------------------------
// K1: SSM scan + D-skip + gelu(tanh), reads x (B,L,H) directly.
// Block = (b, h0..h0+3), one warp per h. Writes (hi,lo) fp16 pairs (B,H,L).
// ---------------------------------------------------------------------------
__global__ __launch_bounds__(128) void scan_kernel(
    const float* __restrict__ x,
    const float* __restrict__ log_dt, const float* __restrict__ A_re,
    const float* __restrict__ A_im, const float* __restrict__ C_re,
    const float* __restrict__ C_im, const float* __restrict__ D_skip) {
    int warp = threadIdx.x >> 5, lane = threadIdx.x & 31;
    int b = blockIdx.x >> 7;
    int h0 = (blockIdx.x & 127) * 4;
    int h = h0 + warp;

    __shared__ ull us[4][32];
    __shared__ ull P2[4][32 * 33];
    ull* Pw = P2[warp];
    ull* uw = us[warp];

    float dt = expf(log_dt[h]);
    float wr_[2], wi_[2], c2r_[2], c2i_[2];
#pragma unroll
    for (int s = 0; s < 2; s++) {
        int n = lane + 32 * s;
        float ar = A_re[h * NN + n], ai = A_im[h * NN + n];
        float dr = dt * ar, di = dt * ai;
        float e = expf(dr);
        float sn, cs; sincosf(di, &sn, &cs);
        float wre = e * cs, wim = e * sn;
        float inv = 1.0f / (ar * ar + ai * ai);
        float qr = ((wre - 1.0f) * ar + wim * ai) * inv;
        float qi = (wim * ar - (wre - 1.0f) * ai) * inv;
        float cr = C_re[h * NN + n], ci = C_im[h * NN + n];
        c2r_[s] = 2.0f * (cr * qr - ci * qi);
        c2i_[s] = 2.0f * (cr * qi + ci * qr);
        wr_[s] = wre; wi_[s] = wim;
    }
    ull Wre  = pk(wr_[0], wr_[1]);
    ull Wim  = pk(wi_[0], wi_[1]);
    ull nWim = pk(-wi_[0], -wi_[1]);
    ull C2r  = pk(c2r_[0], c2r_[1]);
    ull nC2i = pk(-c2i_[0], -c2i_[1]);
    ull sre = pk(0.f, 0.f), sim = pk(0.f, 0.f);
    float Dh = D_skip[h];

    const float* xb = x + ((long)b * LL) * HH + h0;
    __half2* yb = g_yh + ((long)(b * HH + h)) * LL;

    for (int l0 = 0; l0 < LL; l0 += 32) {
        // all 4 warps load identical lines; each keeps its own h component
        float4 v = *(const float4*)(xb + (long)(l0 + lane) * HH);
        float umine = (warp == 0) ? v.x : (warp == 1) ? v.y : (warp == 2) ? v.z : v.w;
        uw[lane] = pk(umine, umine);
        __syncwarp();
#pragma unroll
        for (int t = 0; t < 32; t++) {
            ull up = uw[t];
            ull tre = fma2(nWim, sim, up);
            ull srn = fma2(Wre, sre, tre);
            ull tim = mul2(Wim, sre);
            sim = fma2(Wre, sim, tim);
            sre = srn;
            ull pp = mul2(C2r, sre);
            Pw[t * 33 + lane] = fma2(nC2i, sim, pp);
        }
        __syncwarp();
        // packed reduction over this lane's step
        const ull* row = &Pw[lane * 33];
        ull a0 = row[0], a1 = row[1], a2 = row[2], a3 = row[3];
#pragma unroll
        for (int i = 4; i < 32; i += 4) {
            a0 = add2(a0, row[i]);
            a1 = add2(a1, row[i + 1]);
            a2 = add2(a2, row[i + 2]);
            a3 = add2(a3, row[i + 3]);
        }
        a0 = add2(add2(a0, a1), add2(a2, a3));
        float ax, ay; upk(a0, ax, ay);
        float yv = ax + ay + Dh * umine;
        float t3 = yv * yv * yv;
        float g = 0.5f * yv * (1.0f + tanhf(0.7978845608028654f * (yv + 0.044715f * t3)));
        __half hi, lo; hilo(g, hi, lo);
        yb[l0 + lane] = __halves2half2(hi, lo);
        __syncwarp();
    }
}

// ---------------------------------------------------------------------------
// K2: g_yh (B,H,L) half2 -> Ac1[p=(b,l)][1024] fp16 (hi, lo), transposed
// ---------------------------------------------------------------------------
__global__ __launch_bounds__(256) void tconv_kernel() {
    __shared__ uint32_t t[32][33];
    int b = blockIdx.z;
    int l0 = blockIdx.x * 32;
    int h0 = blockIdx.y * 32;
    int tx = threadIdx.x, ty = threadIdx.y;  // 32 x 8
    const uint32_t* Y = (const uint32_t*)g_yh;
#pragma unroll
    for (int j = 0; j < 4; j++)
        t[ty + 8 * j][tx] = Y[((long)(b * HH + h0 + ty + 8 * j)) * LL + l0 + tx];
    __syncthreads();
#pragma unroll
    for (int j = 0; j < 4; j++) {
        int l = ty + 8 * j;
        __half2 v = *(__half2*)&t[tx][l];
        long p = (long)b * LL + l0 + l;
        long base = p * KK + h0 + tx;
        g_Ac1[base] = __low2half(v);
        g_Ac1[base + 512] = __high2half(v);
    }
}

// ---------------------------------------------------------------------------
// K3: weight convert  W[F][512] fp32 -> Wc[F or p(F)][1024] fp16 (hi, hi)
// PERM: 0 = identity rows, 1 = GLU-interleave p(f) = (f&511)*2 + (f>>9)
// ---------------------------------------------------------------------------
template <int PERM>
__global__ __launch_bounds__(256) void wconv_kernel(const float* __restrict__ W,
                                                    __half* __restrict__ Wc) {
    int idx = blockIdx.x * 256 + threadIdx.x;
    int f = idx >> 9, k = idx & 511;
    float v = W[idx];
    __half h = __float2half_rn(v);
    int fo = PERM ? ((f & 511) * 2 + (f >> 9)) : f;
    long base = (long)fo * KK + k;
    Wc[base] = h; Wc[base + 512] = h;
}

// ---------------------------------------------------------------------------
// HMMA GEMM:  C[M,N] = A[M,1024] @ B[N,1024]^T  (fp16 in, fp32 accum)
// BM=BN=128, BK=64, 3-stage cp.async, SW128 swizzle, mma.sync m16n8k16.
// EPI: 1 = fp32 + bias, 2 = fp16 hi/lo + bias + relu, 3 = GLU (paired cols)
// ---------------------------------------------------------------------------
#define STG_SZ 32768            // 16KB A + 16KB B per stage
#define GSMEM  (3 * STG_SZ)     // 98304
#define KTILES (KK / 64)        // 16

__device__ __forceinline__ void cp_async16(uint32_t dst, const void* src) {
    asm volatile("cp.async.cg.shared.global [%0], [%1], 16;" :: "r"(dst), "l"(src));
}
#define CP_COMMIT() asm volatile("cp.async.commit_group;" ::: "memory")
#define CP_WAIT1()  asm volatile("cp.async.wait_group 1;" ::: "memory")

__device__ __forceinline__ void ldsm4(uint32_t a, uint32_t& r0, uint32_t& r1,
                                      uint32_t& r2, uint32_t& r3) {
    asm volatile("ldmatrix.sync.aligned.m8n8.x4.shared.b16 {%0,%1,%2,%3}, [%4];"
                 : "=r"(r0), "=r"(r1), "=r"(r2), "=r"(r3) : "r"(a));
}
__device__ __forceinline__ void mma16816(float* c, const uint32_t* a, uint32_t b0, uint32_t b1) {
    asm volatile("mma.sync.aligned.m16n8k16.row.col.f32.f16.f16.f32 "
                 "{%0,%1,%2,%3},{%4,%5,%6,%7},{%8,%9},{%0,%1,%2,%3};"
                 : "+f"(c[0]), "+f"(c[1]), "+f"(c[2]), "+f"(c[3])
                 : "r"(a[0]), "r"(a[1]), "r"(a[2]), "r"(a[3]), "r"(b0), "r"(b1));
}

template <int EPI>
__global__ __launch_bounds__(256)
void mma_gemm(const __half* __restrict__ A, const __half* __restrict__ Bw,
              const float* __restrict__ bias, void* __restrict__ Cout, int ldc) {
    extern __shared__ char smem[];
    uint32_t sb = (uint32_t)__cvta_generic_to_shared(smem);
    int tid = threadIdx.x, wid = tid >> 5, lane = tid & 31;
    int wm = wid & 1, wn = wid >> 1;
    long m0 = (long)blockIdx.x * 128;
    long n0 = (long)blockIdx.y * 128;

    auto load_tile = [&](int t, int s) {
        long k0 = (long)t * 64;
        uint32_t Ad = sb + s * STG_SZ;
        uint32_t Bd = Ad + 16384;
        const char* Ag = (const char*)(A + m0 * KK + k0);
        const char* Bg = (const char*)(Bw + n0 * KK + k0);
#pragma unroll
        for (int i = 0; i < 4; i++) {
            int e = tid + i * 256;
            int r = e >> 3, c = e & 7;
            uint32_t off = r * 128 + ((c ^ (r & 7)) << 4);
            cp_async16(Ad + off, Ag + (long)r * (KK * 2) + c * 16);
            cp_async16(Bd + off, Bg + (long)r * (KK * 2) + c * 16);
        }
    };

    float acc[16][4];
#pragma unroll
    for (int i = 0; i < 16; i++)
#pragma unroll
        for (int j = 0; j < 4; j++) acc[i][j] = 0.0f;

    load_tile(0, 0); CP_COMMIT();
    load_tile(1, 1); CP_COMMIT();

    int arow = wm * 64 + (lane & 15);
    int achk = lane >> 4;
    int brow = wn * 32 + (lane & 7) + (((lane >> 4) & 1) << 3);
    int bchk = (lane >> 3) & 1;

    for (int t = 0; t < KTILES; t++) {
        CP_WAIT1();
        __syncthreads();
        int tn = t + 2;
        if (tn < KTILES) load_tile(tn, tn % 3);
        CP_COMMIT();

        uint32_t Ab = sb + (t % 3) * STG_SZ;
        uint32_t Bb = Ab + 16384;
#pragma unroll
        for (int ks = 0; ks < 4; ks++) {
            uint32_t af[4][4], bf[2][4];
#pragma unroll
            for (int mt = 0; mt < 4; mt++) {
                int r = arow + mt * 16;
                int c = 2 * ks + achk;
                ldsm4(Ab + r * 128 + ((c ^ (r & 7)) << 4),
                      af[mt][0], af[mt][1], af[mt][2], af[mt][3]);
            }
#pragma unroll
            for (int np = 0; np < 2; np++) {
                int r = brow + np * 16;
                int c = 2 * ks + bchk;
                ldsm4(Bb + r * 128 + ((c ^ (r & 7)) << 4),
                      bf[np][0], bf[np][1], bf[np][2], bf[np][3]);
            }
#pragma unroll
            for (int mt = 0; mt < 4; mt++)
#pragma unroll
                for (int nt = 0; nt < 4; nt++)
                    mma16816(acc[mt * 4 + nt], af[mt],
                             bf[nt >> 1][(nt & 1) * 2], bf[nt >> 1][(nt & 1) * 2 + 1]);
        }
        __syncthreads();
    }

    // ---- epilogue ----
    int rbase = (int)m0 + wm * 64 + (lane >> 2);
    int cbase = (int)n0 + wn * 32 + (lane & 3) * 2;
#pragma unroll
    for (int mt = 0; mt < 4; mt++) {
#pragma unroll
        for (int nt = 0; nt < 4; nt++) {
            float* d = acc[mt * 4 + nt];
            int col = cbase + nt * 8;
            int row0 = rbase + mt * 16, row1 = row0 + 8;
            if (EPI == 1) {
                float b0 = bias[col], b1 = bias[col + 1];
                float* C = (float*)Cout;
                *(float2*)&C[(long)row0 * ldc + col] = make_float2(d[0] + b0, d[1] + b1);
                *(float2*)&C[(long)row1 * ldc + col] = make_float2(d[2] + b0, d[3] + b1);
            } else if (EPI == 2) {
                float b0 = bias[col], b1 = bias[col + 1];
                __half* C = (__half*)Cout;
                float v00 = fmaxf(d[0] + b0, 0.f), v01 = fmaxf(d[1] + b1, 0.f);
                float v10 = fmaxf(d[2] + b0, 0.f), v11 = fmaxf(d[3] + b1, 0.f);
                __half h00, l00, h01, l01, h10, l10, h11, l11;
                hilo(v00, h00, l00); hilo(v01, h01, l01);
                hilo(v10, h10, l10); hilo(v11, h11, l11);
                long base0 = (long)row0 * KK + col;
                long base1 = (long)row1 * KK + col;
                *(__half2*)&C[base0]       = __halves2half2(h00, h01);
                *(__half2*)&C[base0 + 512] = __halves2half2(l00, l01);
                *(__half2*)&C[base1]       = __halves2half2(h10, h11);
                *(__half2*)&C[base1 + 512] = __halves2half2(l10, l11);
            } else {
                // EPI==3: paired cols = (a_h, g_h); glu = a * sigmoid(g)
                int h = col >> 1;
                float ba = bias[h], bg = bias[512 + h];
                float a0 = d[0] + ba, gg0 = d[1] + bg;
                float a1 = d[2] + ba, gg1 = d[3] + bg;
                float v0 = a0 * (1.0f / (1.0f + expf(-gg0)));
                float v1 = a1 * (1.0f / (1.0f + expf(-gg1)));
                float* C = (float*)Cout;
                C[(long)row0 * HH + h] = v0;
                C[(long)row1 * HH + h] = v1;
            }
        }
    }
}

// ---------------------------------------------------------------------------
// Block reduce (128 threads) for two values
// ---------------------------------------------------------------------------
__device__ __forceinline__ void block_reduce2(float& a, float& b) {
    __shared__ float sa[4], sb2[4];
#pragma unroll
    for (int o = 16; o; o >>= 1) {
        a += __shfl_xor_sync(0xffffffffu, a, o);
        b += __shfl_xor_sync(0xffffffffu, b, o);
    }
    int w = threadIdx.x >> 5, l = threadIdx.x & 31;
    if (l == 0) { sa[w] = a; sb2[w] = b; }
    __syncthreads();
    a = sa[0] + sa[1] + sa[2] + sa[3];
    b = sb2[0] + sb2[1] + sb2[2] + sb2[3];
}

// ---------------------------------------------------------------------------
// K5: residual + LayerNorm1 -> g_xn (fp32) + g_xnc (fp16 hi/lo)
// ---------------------------------------------------------------------------
__global__ __launch_bounds__(128) void res_ln1_kernel(
    const float* __restrict__ x, const float* __restrict__ g1,
    const float* __restrict__ beta1) {
    long p = blockIdx.x;
    const float* gr = g_glu + p * HH;
    const float* xr = x + p * HH;
    float r[4];
    float sum = 0.f, sumsq = 0.f;
#pragma unroll
    for (int j = 0; j < 4; j++) {
        int h = threadIdx.x + j * 128;
        float v = xr[h] + gr[h];
        r[j] = v;
        sum += v; sumsq += v * v;
    }
    block_reduce2(sum, sumsq);
    float mu = sum * (1.0f / HH);
    float var = sumsq * (1.0f / HH) - mu * mu;
    float rs = rsqrtf(var + 1e-5f);
    float* xo = g_xn + p * HH;
    __half* xc = g_xnc + p * KK;
#pragma unroll
    for (int j = 0; j < 4; j++) {
        int h = threadIdx.x + j * 128;
        float v = (r[j] - mu) * rs * g1[h] + beta1[h];
        xo[h] = v;
        __half hh, ll; hilo(v, hh, ll);
        xc[h] = hh; xc[512 + h] = ll;
    }
}

// ---------------------------------------------------------------------------
// K8: residual + LayerNorm2 -> d_out
// ---------------------------------------------------------------------------
__global__ __launch_bounds__(128) void ln2_kernel(
    const float* __restrict__ g2, const float* __restrict__ beta2,
    float* __restrict__ out) {
    long p = blockIdx.x;
    const float* xr = g_xn + p * HH;
    const float* yr = g_y3 + p * HH;
    float r[4];
    float sum = 0.f, sumsq = 0.f;
#pragma unroll
    for (int j = 0; j < 4; j++) {
        int h = threadIdx.x + j * 128;
        float v = xr[h] + yr[h];
        r[j] = v;
        sum += v; sumsq += v * v;
    }
    block_reduce2(sum, sumsq);
    float mu = sum * (1.0f / HH);
    float var = sumsq * (1.0f / HH) - mu * mu;
    float rs = rsqrtf(var + 1e-5f);
    float* o = out + p * HH;
#pragma unroll
    for (int j = 0; j < 4; j++) {
        int h = threadIdx.x + j * 128;
        o[h] = (r[j] - mu) * rs * g2[h] + beta2[h];
    }
}

// ---------------------------------------------------------------------------
// Host launch
// ---------------------------------------------------------------------------
extern "C" void kernel_launch(void* const* d_in, const int* in_sizes, int n_in,
                              void* d_out, int out_size) {
    const float* x      = (const float*)d_in[0];
    const float* log_dt = (const float*)d_in[1];
    const float* A_re   = (const float*)d_in[2];
    const float* A_im   = (const float*)d_in[3];
    const float* C_re   = (const float*)d_in[4];
    const float* C_im   = (const float*)d_in[5];
    const float* D_skip = (const float*)d_in[6];
    const float* W_out  = (const float*)d_in[7];
    const float* b_out  = (const float*)d_in[8];
    const float* g1     = (const float*)d_in[9];
    const float* beta1  = (const float*)d_in[10];
    const float* g2     = (const float*)d_in[11];
    const float* beta2  = (const float*)d_in[12];
    const float* W1     = (const float*)d_in[13];
    const float* bc1    = (const float*)d_in[14];
    const float* W2     = (const float*)d_in[15];
    const float* bc2    = (const float*)d_in[16];
    float* out = (float*)d_out;

    __half *p_Ac1, *p_Wc1, *p_Wc2, *p_Wc3, *p_xnc, *p_h1c;
    float *p_glu, *p_y3;
    cudaGetSymbolAddress((void**)&p_Ac1, g_Ac1);
    cudaGetSymbolAddress((void**)&p_Wc1, g_Wc1);
    cudaGetSymbolAddress((void**)&p_Wc2, g_Wc2);
    cudaGetSymbolAddress((void**)&p_Wc3, g_Wc3);
    cudaGetSymbolAddress((void**)&p_xnc, g_xnc);
    cudaGetSymbolAddress((void**)&p_h1c, g_h1c);
    cudaGetSymbolAddress((void**)&p_glu, g_glu);
    cudaGetSymbolAddress((void**)&p_y3, g_y3);

    cudaFuncSetAttribute(mma_gemm<1>, cudaFuncAttributeMaxDynamicSharedMemorySize, GSMEM);
    cudaFuncSetAttribute(mma_gemm<2>, cudaFuncAttributeMaxDynamicSharedMemorySize, GSMEM);
    cudaFuncSetAttribute(mma_gemm<3>, cudaFuncAttributeMaxDynamicSharedMemorySize, GSMEM);

    // 1) scan (reads x directly) -> g_yh
    scan_kernel<<<BB * HH / 4, 128>>>(x, log_dt, A_re, A_im, C_re, C_im, D_skip);

    // 2) yh -> Ac1 (transpose + hi/lo)
    tconv_kernel<<<dim3(LL / 32, HH / 32, BB), dim3(32, 8)>>>();

    // 3) W_out permuted conversion
    wconv_kernel<1><<<(1024 * 512) / 256, 256>>>(W_out, p_Wc1);

    // 4) GEMM1 + fused GLU  -> g_glu  (N=1024 interleaved a/g)   [profiled slot]
    mma_gemm<3><<<dim3(PP / 128, 1024 / 128), 256, GSMEM>>>(p_Ac1, p_Wc1, b_out, p_glu, 0);

    // 5) W1 conversion
    wconv_kernel<0><<<(512 * 512) / 256, 256>>>(W1, p_Wc2);

    // 6) residual + LN1 -> g_xn, g_xnc
    res_ln1_kernel<<<PP, 128>>>(x, g1, beta1);

    // 7) GEMM2  h1c = relu(xn @ W1^T + bc1) as fp16 hi/lo
    mma_gemm<2><<<dim3(PP / 128, 512 / 128), 256, GSMEM>>>(p_xnc, p_Wc2, bc1, p_h1c, 0);

    // 8) W2 conversion
    wconv_kernel<0><<<(512 * 512) / 256, 256>>>(W2, p_Wc3);

    // 9) GEMM3  y3 = h1 @ W2^T + bc2
    mma_gemm<1><<<dim3(PP / 128, 512 / 128), 256, GSMEM>>>(p_h1c, p_Wc3, bc2, p_y3, 512);

    // 10) residual + LN2 -> out
    ln2_kernel<<<PP, 128>>>(g2, beta2, out);
}

// round 9
// speedup vs baseline: 2.3112x; 1.2142x over previous
#include <cuda_runtime.h>
#include <cuda_fp16.h>
#include <math.h>
#include <stdint.h>

typedef unsigned long long ull;

// ---------------------------------------------------------------------------
// Problem dims
// ---------------------------------------------------------------------------
#define BB 8
#define LL 2048
#define HH 512
#define NN 64
#define PP (BB * LL)          // 16384 tokens
#define KK 512                // pure fp16, K = H

// ---------------------------------------------------------------------------
// Scratch (device globals — no allocation allowed)
// ---------------------------------------------------------------------------
__device__ __half g_yh[(long)BB * HH * LL];   // gelu(scan+D*u) fp16, (B,H,L)
__device__ __half g_Ac1[(long)PP * KK];       // GEMM1 A
__device__ __half g_Wc1[(long)1024 * KK];     // W_out permuted
__device__ __half g_Wc2[(long)HH * KK];       // W1
__device__ __half g_Wc3[(long)HH * KK];       // W2
__device__ float g_glu[(long)PP * HH];        // GEMM1+GLU out (P, 512)
__device__ float g_xn[(long)PP * HH];         // after res+LN1 (fp32)
__device__ __half g_xnc[(long)PP * KK];       // xn fp16 for GEMM2
__device__ __half g_h1c[(long)PP * KK];       // FFN hidden fp16 for GEMM3
__device__ float g_y3[(long)PP * HH];         // FFN out

// ---------------------------------------------------------------------------
// Packed f32x2 helpers
// ---------------------------------------------------------------------------
__device__ __forceinline__ ull pk(float x, float y) {
    ull r; asm("mov.b64 %0, {%1,%2};" : "=l"(r) : "f"(x), "f"(y)); return r;
}
__device__ __forceinline__ void upk(ull v, float& x, float& y) {
    asm("mov.b64 {%0,%1}, %2;" : "=f"(x), "=f"(y) : "l"(v));
}
__device__ __forceinline__ ull fma2(ull a, ull b, ull c) {
    ull d; asm("fma.rn.f32x2 %0, %1, %2, %3;" : "=l"(d) : "l"(a), "l"(b), "l"(c)); return d;
}
__device__ __forceinline__ ull mul2(ull a, ull b) {
    ull d; asm("mul.rn.f32x2 %0, %1, %2;" : "=l"(d) : "l"(a), "l"(b)); return d;
}
__device__ __forceinline__ ull add2(ull a, ull b) {
    ull d; asm("add.rn.f32x2 %0, %1, %2;" : "=l"(d) : "l"(a), "l"(b)); return d;
}

// ---------------------------------------------------------------------------
// K1: SSM scan + D-skip + gelu(tanh), reads x (B,L,H) directly.
// Block = (b, h0..h0+3), one warp per h. Writes fp16 (B,H,L).
// ---------------------------------------------------------------------------
__global__ __launch_bounds__(128) void scan_kernel(
    const float* __restrict__ x,
    const float* __restrict__ log_dt, const float* __restrict__ A_re,
    const float* __restrict__ A_im, const float* __restrict__ C_re,
    const float* __restrict__ C_im, const float* __restrict__ D_skip) {
    int warp = threadIdx.x >> 5, lane = threadIdx.x & 31;
    int b = blockIdx.x >> 7;
    int h0 = (blockIdx.x & 127) * 4;
    int h = h0 + warp;

    __shared__ ull us[4][32];
    __shared__ ull P2[4][32 * 33];
    ull* Pw = P2[warp];
    ull* uw = us[warp];

    float dt = expf(log_dt[h]);
    float wr_[2], wi_[2], c2r_[2], c2i_[2];
#pragma unroll
    for (int s = 0; s < 2; s++) {
        int n = lane + 32 * s;
        float ar = A_re[h * NN + n], ai = A_im[h * NN + n];
        float dr = dt * ar, di = dt * ai;
        float e = expf(dr);
        float sn, cs; sincosf(di, &sn, &cs);
        float wre = e * cs, wim = e * sn;
        float inv = 1.0f / (ar * ar + ai * ai);
        float qr = ((wre - 1.0f) * ar + wim * ai) * inv;
        float qi = (wim * ar - (wre - 1.0f) * ai) * inv;
        float cr = C_re[h * NN + n], ci = C_im[h * NN + n];
        c2r_[s] = 2.0f * (cr * qr - ci * qi);
        c2i_[s] = 2.0f * (cr * qi + ci * qr);
        wr_[s] = wre; wi_[s] = wim;
    }
    ull Wre  = pk(wr_[0], wr_[1]);
    ull Wim  = pk(wi_[0], wi_[1]);
    ull nWim = pk(-wi_[0], -wi_[1]);
    ull C2r  = pk(c2r_[0], c2r_[1]);
    ull nC2i = pk(-c2i_[0], -c2i_[1]);
    ull sre = pk(0.f, 0.f), sim = pk(0.f, 0.f);
    float Dh = D_skip[h];

    const float* xb = x + ((long)b * LL) * HH + h0;
    __half* yb = g_yh + ((long)(b * HH + h)) * LL;

    for (int l0 = 0; l0 < LL; l0 += 32) {
        // all 4 warps load identical lines; each keeps its own h component
        float4 v = *(const float4*)(xb + (long)(l0 + lane) * HH);
        float umine = (warp == 0) ? v.x : (warp == 1) ? v.y : (warp == 2) ? v.z : v.w;
        uw[lane] = pk(umine, umine);
        __syncwarp();
#pragma unroll
        for (int t = 0; t < 32; t++) {
            ull up = uw[t];
            ull tre = fma2(nWim, sim, up);
            ull srn = fma2(Wre, sre, tre);
            ull tim = mul2(Wim, sre);
            sim = fma2(Wre, sim, tim);
            sre = srn;
            ull pp = mul2(C2r, sre);
            Pw[t * 33 + lane] = fma2(nC2i, sim, pp);
        }
        __syncwarp();
        // packed reduction over this lane's step
        const ull* row = &Pw[lane * 33];
        ull a0 = row[0], a1 = row[1], a2 = row[2], a3 = row[3];
#pragma unroll
        for (int i = 4; i < 32; i += 4) {
            a0 = add2(a0, row[i]);
            a1 = add2(a1, row[i + 1]);
            a2 = add2(a2, row[i + 2]);
            a3 = add2(a3, row[i + 3]);
        }
        a0 = add2(add2(a0, a1), add2(a2, a3));
        float ax, ay; upk(a0, ax, ay);
        float yv = ax + ay + Dh * umine;
        float t3 = yv * yv * yv;
        float g = 0.5f * yv * (1.0f + tanhf(0.7978845608028654f * (yv + 0.044715f * t3)));
        yb[l0 + lane] = __float2half_rn(g);
        __syncwarp();
    }
}

// ---------------------------------------------------------------------------
// K2: g_yh (B,H,L) fp16 -> Ac1[p=(b,l)][512] fp16, transposed
// ---------------------------------------------------------------------------
__global__ __launch_bounds__(256) void tconv_kernel() {
    __shared__ __half t[32][33];
    int b = blockIdx.z;
    int l0 = blockIdx.x * 32;
    int h0 = blockIdx.y * 32;
    int tx = threadIdx.x, ty = threadIdx.y;  // 32 x 8
#pragma unroll
    for (int j = 0; j < 4; j++)
        t[ty + 8 * j][tx] = g_yh[((long)(b * HH + h0 + ty + 8 * j)) * LL + l0 + tx];
    __syncthreads();
#pragma unroll
    for (int j = 0; j < 4; j++) {
        int l = ty + 8 * j;
        long p = (long)b * LL + l0 + l;
        g_Ac1[p * KK + h0 + tx] = t[tx][l];
    }
}

// ---------------------------------------------------------------------------
// K3: weight convert  W[F][512] fp32 -> Wc[F or p(F)][512] fp16
// PERM: 0 = identity rows, 1 = GLU-interleave p(f) = (f&511)*2 + (f>>9)
// ---------------------------------------------------------------------------
template <int PERM>
__global__ __launch_bounds__(256) void wconv_kernel(const float* __restrict__ W,
                                                    __half* __restrict__ Wc) {
    int idx = blockIdx.x * 256 + threadIdx.x;
    int f = idx >> 9, k = idx & 511;
    float v = W[idx];
    int fo = PERM ? ((f & 511) * 2 + (f >> 9)) : f;
    Wc[(long)fo * KK + k] = __float2half_rn(v);
}

// ---------------------------------------------------------------------------
// HMMA GEMM:  C[M,N] = A[M,512] @ B[N,512]^T  (fp16 in, fp32 accum)
// BM=BN=128, BK=64, 3-stage cp.async, SW128 swizzle, mma.sync m16n8k16.
// EPI: 1 = fp32 + bias, 2 = fp16 + bias + relu, 3 = GLU (paired cols)
// ---------------------------------------------------------------------------
#define STG_SZ 32768            // 16KB A + 16KB B per stage
#define GSMEM  (3 * STG_SZ)     // 98304
#define KTILES (KK / 64)        // 8

__device__ __forceinline__ void cp_async16(uint32_t dst, const void* src) {
    asm volatile("cp.async.cg.shared.global [%0], [%1], 16;" :: "r"(dst), "l"(src));
}
#define CP_COMMIT() asm volatile("cp.async.commit_group;" ::: "memory")
#define CP_WAIT1()  asm volatile("cp.async.wait_group 1;" ::: "memory")

__device__ __forceinline__ void ldsm4(uint32_t a, uint32_t& r0, uint32_t& r1,
                                      uint32_t& r2, uint32_t& r3) {
    asm volatile("ldmatrix.sync.aligned.m8n8.x4.shared.b16 {%0,%1,%2,%3}, [%4];"
                 : "=r"(r0), "=r"(r1), "=r"(r2), "=r"(r3) : "r"(a));
}
__device__ __forceinline__ void mma16816(float* c, const uint32_t* a, uint32_t b0, uint32_t b1) {
    asm volatile("mma.sync.aligned.m16n8k16.row.col.f32.f16.f16.f32 "
                 "{%0,%1,%2,%3},{%4,%5,%6,%7},{%8,%9},{%0,%1,%2,%3};"
                 : "+f"(c[0]), "+f"(c[1]), "+f"(c[2]), "+f"(c[3])
                 : "r"(a[0]), "r"(a[1]), "r"(a[2]), "r"(a[3]), "r"(b0), "r"(b1));
}

template <int EPI>
__global__ __launch_bounds__(256)
void mma_gemm(const __half* __restrict__ A, const __half* __restrict__ Bw,
              const float* __restrict__ bias, void* __restrict__ Cout, int ldc) {
    extern __shared__ char smem[];
    uint32_t sb = (uint32_t)__cvta_generic_to_shared(smem);
    int tid = threadIdx.x, wid = tid >> 5, lane = tid & 31;
    int wm = wid & 1, wn = wid >> 1;
    long m0 = (long)blockIdx.x * 128;
    long n0 = (long)blockIdx.y * 128;

    auto load_tile = [&](int t, int s) {
        long k0 = (long)t * 64;
        uint32_t Ad = sb + s * STG_SZ;
        uint32_t Bd = Ad + 16384;
        const char* Ag = (const char*)(A + m0 * KK + k0);
        const char* Bg = (const char*)(Bw + n0 * KK + k0);
#pragma unroll
        for (int i = 0; i < 4; i++) {
            int e = tid + i * 256;
            int r = e >> 3, c = e & 7;
            uint32_t off = r * 128 + ((c ^ (r & 7)) << 4);
            cp_async16(Ad + off, Ag + (long)r * (KK * 2) + c * 16);
            cp_async16(Bd + off, Bg + (long)r * (KK * 2) + c * 16);
        }
    };

    float acc[16][4];
#pragma unroll
    for (int i = 0; i < 16; i++)
#pragma unroll
        for (int j = 0; j < 4; j++) acc[i][j] = 0.0f;

    load_tile(0, 0); CP_COMMIT();
    load_tile(1, 1); CP_COMMIT();

    int arow = wm * 64 + (lane & 15);
    int achk = lane >> 4;
    int brow = wn * 32 + (lane & 7) + (((lane >> 4) & 1) << 3);
    int bchk = (lane >> 3) & 1;

    for (int t = 0; t < KTILES; t++) {
        CP_WAIT1();
        __syncthreads();
        int tn = t + 2;
        if (tn < KTILES) load_tile(tn, tn % 3);
        CP_COMMIT();

        uint32_t Ab = sb + (t % 3) * STG_SZ;
        uint32_t Bb = Ab + 16384;
#pragma unroll
        for (int ks = 0; ks < 4; ks++) {
            uint32_t af[4][4], bf[2][4];
#pragma unroll
            for (int mt = 0; mt < 4; mt++) {
                int r = arow + mt * 16;
                int c = 2 * ks + achk;
                ldsm4(Ab + r * 128 + ((c ^ (r & 7)) << 4),
                      af[mt][0], af[mt][1], af[mt][2], af[mt][3]);
            }
#pragma unroll
            for (int np = 0; np < 2; np++) {
                int r = brow + np * 16;
                int c = 2 * ks + bchk;
                ldsm4(Bb + r * 128 + ((c ^ (r & 7)) << 4),
                      bf[np][0], bf[np][1], bf[np][2], bf[np][3]);
            }
#pragma unroll
            for (int mt = 0; mt < 4; mt++)
#pragma unroll
                for (int nt = 0; nt < 4; nt++)
                    mma16816(acc[mt * 4 + nt], af[mt],
                             bf[nt >> 1][(nt & 1) * 2], bf[nt >> 1][(nt & 1) * 2 + 1]);
        }
        __syncthreads();
    }

    // ---- epilogue ----
    int rbase = (int)m0 + wm * 64 + (lane >> 2);
    int cbase = (int)n0 + wn * 32 + (lane & 3) * 2;
#pragma unroll
    for (int mt = 0; mt < 4; mt++) {
#pragma unroll
        for (int nt = 0; nt < 4; nt++) {
            float* d = acc[mt * 4 + nt];
            int col = cbase + nt * 8;
            int row0 = rbase + mt * 16, row1 = row0 + 8;
            if (EPI == 1) {
                float b0 = bias[col], b1 = bias[col + 1];
                float* C = (float*)Cout;
                *(float2*)&C[(long)row0 * ldc + col] = make_float2(d[0] + b0, d[1] + b1);
                *(float2*)&C[(long)row1 * ldc + col] = make_float2(d[2] + b0, d[3] + b1);
            } else if (EPI == 2) {
                float b0 = bias[col], b1 = bias[col + 1];
                __half* C = (__half*)Cout;
                float v00 = fmaxf(d[0] + b0, 0.f), v01 = fmaxf(d[1] + b1, 0.f);
                float v10 = fmaxf(d[2] + b0, 0.f), v11 = fmaxf(d[3] + b1, 0.f);
                *(__half2*)&C[(long)row0 * KK + col] =
                    __halves2half2(__float2half_rn(v00), __float2half_rn(v01));
                *(__half2*)&C[(long)row1 * KK + col] =
                    __halves2half2(__float2half_rn(v10), __float2half_rn(v11));
            } else {
                // EPI==3: paired cols = (a_h, g_h); glu = a * sigmoid(g)
                int h = col >> 1;
                float ba = bias[h], bg = bias[512 + h];
                float a0 = d[0] + ba, gg0 = d[1] + bg;
                float a1 = d[2] + ba, gg1 = d[3] + bg;
                float v0 = a0 * (1.0f / (1.0f + expf(-gg0)));
                float v1 = a1 * (1.0f / (1.0f + expf(-gg1)));
                float* C = (float*)Cout;
                C[(long)row0 * HH + h] = v0;
                C[(long)row1 * HH + h] = v1;
            }
        }
    }
}

// ---------------------------------------------------------------------------
// Block reduce (128 threads) for two values
// ---------------------------------------------------------------------------
__device__ __forceinline__ void block_reduce2(float& a, float& b) {
    __shared__ float sa[4], sb2[4];
#pragma unroll
    for (int o = 16; o; o >>= 1) {
        a += __shfl_xor_sync(0xffffffffu, a, o);
        b += __shfl_xor_sync(0xffffffffu, b, o);
    }
    int w = threadIdx.x >> 5, l = threadIdx.x & 31;
    if (l == 0) { sa[w] = a; sb2[w] = b; }
    __syncthreads();
    a = sa[0] + sa[1] + sa[2] + sa[3];
    b = sb2[0] + sb2[1] + sb2[2] + sb2[3];
}

// ---------------------------------------------------------------------------
// K5: residual + LayerNorm1 -> g_xn (fp32) + g_xnc (fp16)
// ---------------------------------------------------------------------------
__global__ __launch_bounds__(128) void res_ln1_kernel(
    const float* __restrict__ x, const float* __restrict__ g1,
    const float* __restrict__ beta1) {
    long p = blockIdx.x;
    const float* gr = g_glu + p * HH;
    const float* xr = x + p * HH;
    float r[4];
    float sum = 0.f, sumsq = 0.f;
#pragma unroll
    for (int j = 0; j < 4; j++) {
        int h = threadIdx.x + j * 128;
        float v = xr[h] + gr[h];
        r[j] = v;
        sum += v; sumsq += v * v;
    }
    block_reduce2(sum, sumsq);
    float mu = sum * (1.0f / HH);
    float var = sumsq * (1.0f / HH) - mu * mu;
    float rs = rsqrtf(var + 1e-5f);
    float* xo = g_xn + p * HH;
    __half* xc = g_xnc + p * KK;
#pragma unroll
    for (int j = 0; j < 4; j++) {
        int h = threadIdx.x + j * 128;
        float v = (r[j] - mu) * rs * g1[h] + beta1[h];
        xo[h] = v;
        xc[h] = __float2half_rn(v);
    }
}

// ---------------------------------------------------------------------------
// K8: residual + LayerNorm2 -> d_out
// ---------------------------------------------------------------------------
__global__ __launch_bounds__(128) void ln2_kernel(
    const float* __restrict__ g2, const float* __restrict__ beta2,
    float* __restrict__ out) {
    long p = blockIdx.x;
    const float* xr = g_xn + p * HH;
    const float* yr = g_y3 + p * HH;
    float r[4];
    float sum = 0.f, sumsq = 0.f;
#pragma unroll
    for (int j = 0; j < 4; j++) {
        int h = threadIdx.x + j * 128;
        float v = xr[h] + yr[h];
        r[j] = v;
        sum += v; sumsq += v * v;
    }
    block_reduce2(sum, sumsq);
    float mu = sum * (1.0f / HH);
    float var = sumsq * (1.0f / HH) - mu * mu;
    float rs = rsqrtf(var + 1e-5f);
    float* o = out + p * HH;
#pragma unroll
    for (int j = 0; j < 4; j++) {
        int h = threadIdx.x + j * 128;
        o[h] = (r[j] - mu) * rs * g2[h] + beta2[h];
    }
}

// ---------------------------------------------------------------------------
// Host launch
// ---------------------------------------------------------------------------
extern "C" void kernel_launch(void* const* d_in, const int* in_sizes, int n_in,
                              void* d_out, int out_size) {
    const float* x      = (const float*)d_in[0];
    const float* log_dt = (const float*)d_in[1];
    const float* A_re   = (const float*)d_in[2];
    const float* A_im   = (const float*)d_in[3];
    const float* C_re   = (const float*)d_in[4];
    const float* C_im   = (const float*)d_in[5];
    const float* D_skip = (const float*)d_in[6];
    const float* W_out  = (const float*)d_in[7];
    const float* b_out  = (const float*)d_in[8];
    const float* g1     = (const float*)d_in[9];
    const float* beta1  = (const float*)d_in[10];
    const float* g2     = (const float*)d_in[11];
    const float* beta2  = (const float*)d_in[12];
    const float* W1     = (const float*)d_in[13];
    const float* bc1    = (const float*)d_in[14];
    const float* W2     = (const float*)d_in[15];
    const float* bc2    = (const float*)d_in[16];
    float* out = (float*)d_out;

    __half *p_Ac1, *p_Wc1, *p_Wc2, *p_Wc3, *p_xnc, *p_h1c;
    float *p_glu, *p_y3;
    cudaGetSymbolAddress((void**)&p_Ac1, g_Ac1);
    cudaGetSymbolAddress((void**)&p_Wc1, g_Wc1);
    cudaGetSymbolAddress((void**)&p_Wc2, g_Wc2);
    cudaGetSymbolAddress((void**)&p_Wc3, g_Wc3);
    cudaGetSymbolAddress((void**)&p_xnc, g_xnc);
    cudaGetSymbolAddress((void**)&p_h1c, g_h1c);
    cudaGetSymbolAddress((void**)&p_glu, g_glu);
    cudaGetSymbolAddress((void**)&p_y3, g_y3);

    cudaFuncSetAttribute(mma_gemm<1>, cudaFuncAttributeMaxDynamicSharedMemorySize, GSMEM);
    cudaFuncSetAttribute(mma_gemm<2>, cudaFuncAttributeMaxDynamicSharedMemorySize, GSMEM);
    cudaFuncSetAttribute(mma_gemm<3>, cudaFuncAttributeMaxDynamicSharedMemorySize, GSMEM);

    // 1) scan (reads x directly) -> g_yh
    scan_kernel<<<BB * HH / 4, 128>>>(x, log_dt, A_re, A_im, C_re, C_im, D_skip);

    // 2) yh -> Ac1 (transpose)
    tconv_kernel<<<dim3(LL / 32, HH / 32, BB), dim3(32, 8)>>>();

    // 3) W_out permuted conversion
    wconv_kernel<1><<<(1024 * 512) / 256, 256>>>(W_out, p_Wc1);

    // 4) GEMM1 + fused GLU  -> g_glu  (N=1024 interleaved a/g)   [profiled slot]
    mma_gemm<3><<<dim3(PP / 128, 1024 / 128), 256, GSMEM>>>(p_Ac1, p_Wc1, b_out, p_glu, 0);

    // 5) W1 conversion
    wconv_kernel<0><<<(512 * 512) / 256, 256>>>(W1, p_Wc2);

    // 6) residual + LN1 -> g_xn, g_xnc
    res_ln1_kernel<<<PP, 128>>>(x, g1, beta1);

    // 7) GEMM2  h1c = relu(xn @ W1^T + bc1) as fp16
    mma_gemm<2><<<dim3(PP / 128, 512 / 128), 256, GSMEM>>>(p_xnc, p_Wc2, bc1, p_h1c, 0);

    // 8) W2 conversion
    wconv_kernel<0><<<(512 * 512) / 256, 256>>>(W2, p_Wc3);

    // 9) GEMM3  y3 = h1 @ W2^T + bc2
    mma_gemm<1><<<dim3(PP / 128, 512 / 128), 256, GSMEM>>>(p_h1c, p_Wc3, bc2, p_y3, 512);

    // 10) residual + LN2 -> out
    ln2_kernel<<<PP, 128>>>(g2, beta2, out);
}